// round 1
// baseline (speedup 1.0000x reference)
#include <cuda_runtime.h>
#include <cstdint>

#define BATCHN 4
#define SEQLEN 2048
#define DMODEL 1024
#define DINNER 2048
#define DSTATE 16
#define DTRANK 64
#define NROWS (BATCHN*SEQLEN)   /* 8192 */

// ---------------- scratch (static device globals; no allocations) ----------------
__device__ float g_xz  [NROWS*4096];    // in_proj output (x | z)
__device__ float g_x   [NROWS*DINNER];  // conv+silu output
__device__ float g_zs  [NROWS*DINNER];  // silu(z)
__device__ float g_xdbl[NROWS*96];      // x @ x_proj_w  (dt_in | B | C)
__device__ float g_dt  [NROWS*DINNER];  // softplus(dt_in @ dt_proj_w + b)
__device__ float g_y   [NROWS*DINNER];  // scan output * silu(z)

// ---------------- helpers ----------------
__device__ __forceinline__ float to_tf32(float x) {
    uint32_t u;
    asm("cvt.rna.tf32.f32 %0, %1;" : "=r"(u) : "f"(x));
    return __uint_as_float(u);
}

__device__ __forceinline__ void mma8(float* d, const uint32_t* a, const uint32_t* b) {
    asm volatile(
        "mma.sync.aligned.m16n8k8.row.col.f32.tf32.tf32.f32 "
        "{%0,%1,%2,%3}, {%4,%5,%6,%7}, {%8,%9}, {%0,%1,%2,%3};\n"
        : "+f"(d[0]), "+f"(d[1]), "+f"(d[2]), "+f"(d[3])
        : "r"(a[0]), "r"(a[1]), "r"(a[2]), "r"(a[3]), "r"(b[0]), "r"(b[1]));
}

__device__ __forceinline__ float softplusf(float v) {
    return fmaxf(v, 0.f) + log1pf(__expf(-fabsf(v)));
}

// ---------------- generic tf32 GEMM: C = epi(A[M,K] @ B[K,N]) ----------------
// BM=128, BN=128, BK=16, 256 threads, 8 warps (2x4), warp tile 64x32.
// SPLIT: 3xTF32 (hi*hi + hi*lo + lo*hi) for ~fp32 accuracy.
// EPI: 0 = none, 1 = softplus(v + bias[col])
template<bool SPLIT, int EPI>
__global__ void __launch_bounds__(256) gemm_tf32(
    const float* __restrict__ A, const float* __restrict__ B,
    const float* __restrict__ bias, float* __restrict__ C,
    int M, int N, int K, int lda, int ldb, int ldc)
{
    __shared__ float As [16][132];
    __shared__ float Bs [16][132];
    __shared__ float Asl[SPLIT ? 16 : 1][SPLIT ? 132 : 1];
    __shared__ float Bsl[SPLIT ? 16 : 1][SPLIT ? 132 : 1];

    const int tid  = threadIdx.x;
    const int lane = tid & 31;
    const int w    = tid >> 5;
    const int wr   = w >> 2;       // 0..1
    const int wc   = w & 3;        // 0..3
    const int tig  = lane & 3;
    const int g    = lane >> 2;
    const int m0   = blockIdx.y * 128;
    const int n0   = blockIdx.x * 128;

    float acc[4][4][4];
    #pragma unroll
    for (int i = 0; i < 4; i++)
        #pragma unroll
        for (int j = 0; j < 4; j++)
            #pragma unroll
            for (int q = 0; q < 4; q++) acc[i][j][q] = 0.f;

    for (int k0 = 0; k0 < K; k0 += 16) {
        __syncthreads();
        // ---- load A tile (128 x 16), store k-major (transposed) ----
        #pragma unroll
        for (int i = 0; i < 2; i++) {
            int j  = tid + i * 256;      // 0..511
            int r  = j >> 2;             // 0..127
            int c4 = j & 3;              // 0..3
            float4 v = *reinterpret_cast<const float4*>(A + (size_t)(m0 + r) * lda + k0 + c4 * 4);
            float h0 = to_tf32(v.x), h1 = to_tf32(v.y), h2 = to_tf32(v.z), h3 = to_tf32(v.w);
            As[c4*4+0][r] = h0; As[c4*4+1][r] = h1;
            As[c4*4+2][r] = h2; As[c4*4+3][r] = h3;
            if constexpr (SPLIT) {
                Asl[c4*4+0][r] = to_tf32(v.x - h0);
                Asl[c4*4+1][r] = to_tf32(v.y - h1);
                Asl[c4*4+2][r] = to_tf32(v.z - h2);
                Asl[c4*4+3][r] = to_tf32(v.w - h3);
            }
        }
        // ---- load B tile (16 x 128) ----
        #pragma unroll
        for (int i = 0; i < 2; i++) {
            int j  = tid + i * 256;
            int r  = j >> 5;             // 0..15
            int c4 = j & 31;             // 0..31
            int n  = n0 + c4 * 4;
            float4 v;
            if (n + 3 < N) {
                v = *reinterpret_cast<const float4*>(B + (size_t)(k0 + r) * ldb + n);
            } else {
                const float* bp = B + (size_t)(k0 + r) * ldb;
                v.x = (n + 0 < N) ? bp[n + 0] : 0.f;
                v.y = (n + 1 < N) ? bp[n + 1] : 0.f;
                v.z = (n + 2 < N) ? bp[n + 2] : 0.f;
                v.w = (n + 3 < N) ? bp[n + 3] : 0.f;
            }
            float h0 = to_tf32(v.x), h1 = to_tf32(v.y), h2 = to_tf32(v.z), h3 = to_tf32(v.w);
            Bs[r][c4*4+0] = h0; Bs[r][c4*4+1] = h1;
            Bs[r][c4*4+2] = h2; Bs[r][c4*4+3] = h3;
            if constexpr (SPLIT) {
                Bsl[r][c4*4+0] = to_tf32(v.x - h0);
                Bsl[r][c4*4+1] = to_tf32(v.y - h1);
                Bsl[r][c4*4+2] = to_tf32(v.z - h2);
                Bsl[r][c4*4+3] = to_tf32(v.w - h3);
            }
        }
        __syncthreads();

        #pragma unroll
        for (int kk = 0; kk < 16; kk += 8) {
            uint32_t ah[4][4], bh[4][2];
            uint32_t al[4][4], bl[4][2];
            #pragma unroll
            for (int mf = 0; mf < 4; mf++) {
                int mr = wr * 64 + mf * 16 + g;
                ah[mf][0] = __float_as_uint(As[kk +     tig][mr    ]);
                ah[mf][1] = __float_as_uint(As[kk +     tig][mr + 8]);
                ah[mf][2] = __float_as_uint(As[kk + 4 + tig][mr    ]);
                ah[mf][3] = __float_as_uint(As[kk + 4 + tig][mr + 8]);
                if constexpr (SPLIT) {
                    al[mf][0] = __float_as_uint(Asl[kk +     tig][mr    ]);
                    al[mf][1] = __float_as_uint(Asl[kk +     tig][mr + 8]);
                    al[mf][2] = __float_as_uint(Asl[kk + 4 + tig][mr    ]);
                    al[mf][3] = __float_as_uint(Asl[kk + 4 + tig][mr + 8]);
                }
            }
            #pragma unroll
            for (int nf = 0; nf < 4; nf++) {
                int nc = wc * 32 + nf * 8 + g;
                bh[nf][0] = __float_as_uint(Bs[kk +     tig][nc]);
                bh[nf][1] = __float_as_uint(Bs[kk + 4 + tig][nc]);
                if constexpr (SPLIT) {
                    bl[nf][0] = __float_as_uint(Bsl[kk +     tig][nc]);
                    bl[nf][1] = __float_as_uint(Bsl[kk + 4 + tig][nc]);
                }
            }
            #pragma unroll
            for (int mf = 0; mf < 4; mf++)
                #pragma unroll
                for (int nf = 0; nf < 4; nf++) {
                    mma8(acc[mf][nf], ah[mf], bh[nf]);
                    if constexpr (SPLIT) {
                        mma8(acc[mf][nf], ah[mf], bl[nf]);
                        mma8(acc[mf][nf], al[mf], bh[nf]);
                    }
                }
        }
    }

    // ---- epilogue ----
    #pragma unroll
    for (int mf = 0; mf < 4; mf++) {
        int row = m0 + wr * 64 + mf * 16 + g;
        #pragma unroll
        for (int nf = 0; nf < 4; nf++) {
            int col = n0 + wc * 32 + nf * 8 + 2 * tig;
            float v0 = acc[mf][nf][0], v1 = acc[mf][nf][1];
            float v2 = acc[mf][nf][2], v3 = acc[mf][nf][3];
            if (EPI == 1) {
                if (col < N)     { float bb = bias[col];     v0 = softplusf(v0 + bb); v2 = softplusf(v2 + bb); }
                if (col + 1 < N) { float bb = bias[col + 1]; v1 = softplusf(v1 + bb); v3 = softplusf(v3 + bb); }
            }
            float* cp  = C + (size_t)row * ldc + col;
            float* cp2 = cp + (size_t)8 * ldc;
            if (col < N)     { cp[0] = v0; cp2[0] = v2; }
            if (col + 1 < N) { cp[1] = v1; cp2[1] = v3; }
        }
    }
}

// ---------------- causal depthwise conv (K=4) + silu, plus silu(z) ----------------
__global__ void conv_silu_kernel(const float* __restrict__ xz,
                                 const float* __restrict__ cw,
                                 const float* __restrict__ cb,
                                 float* __restrict__ xo,
                                 float* __restrict__ zso)
{
    int idx = blockIdx.x * 256 + threadIdx.x;          // over NROWS*DINNER
    int d   = idx & (DINNER - 1);
    int row = idx >> 11;
    int t   = row & (SEQLEN - 1);

    float w0 = cw[d*4+0], w1 = cw[d*4+1], w2 = cw[d*4+2], w3 = cw[d*4+3];
    size_t base = (size_t)row * 4096 + d;
    float acc = cb[d] + xz[base] * w3;
    if (t >= 1) acc = fmaf(xz[base - 4096],     w2, acc);
    if (t >= 2) acc = fmaf(xz[base - 2 * 4096], w1, acc);
    if (t >= 3) acc = fmaf(xz[base - 3 * 4096], w0, acc);
    xo[idx] = acc * (1.f / (1.f + __expf(-acc)));      // silu

    float zv = xz[(size_t)row * 4096 + DINNER + d];
    zso[idx] = zv * (1.f / (1.f + __expf(-zv)));       // silu(z)
}

// ---------------- selective scan ----------------
// block = 512 threads = 32 channels x 16 states; grid = (64 d-chunks, 4 batches)
// B/C/x/dt/silu(z) staged in SMEM 64 timesteps at a time; h in registers.
__global__ void __launch_bounds__(512) scan_kernel(
    const float* __restrict__ xdbl, const float* __restrict__ xs,
    const float* __restrict__ dts,  const float* __restrict__ zss,
    const float* __restrict__ A_log, const float* __restrict__ Dp,
    float* __restrict__ y)
{
    const int b   = blockIdx.y;
    const int d0  = blockIdx.x * 32;
    const int tid = threadIdx.x;
    const int n   = tid & 15;
    const int ch  = tid >> 4;           // 0..31
    const int d   = d0 + ch;

    __shared__ float sBC[64][32];       // [t][0..15]=B, [t][16..31]=C
    __shared__ float sX [64][32];
    __shared__ float sDT[64][32];
    __shared__ float sZ [64][32];
    __shared__ float sY [64][32];

    const float a  = -__expf(A_log[d * DSTATE + n]);
    const float Dd = Dp[d];
    float h = 0.f;

    const size_t rowbase = (size_t)b * SEQLEN;
    for (int t0 = 0; t0 < SEQLEN; t0 += 64) {
        __syncthreads();
        #pragma unroll
        for (int i = 0; i < 4; i++) {
            int j  = tid + i * 512;      // 0..2047
            int tl = j >> 5, dd = j & 31;
            size_t r = rowbase + t0 + tl;
            sX [tl][dd] = xs [r * DINNER + d0 + dd];
            sDT[tl][dd] = dts[r * DINNER + d0 + dd];
            sZ [tl][dd] = zss[r * DINNER + d0 + dd];
            sBC[tl][dd] = xdbl[r * 96 + DTRANK + dd];   // cols 64..95 = B|C
        }
        __syncthreads();

        #pragma unroll 4
        for (int tl = 0; tl < 64; tl++) {
            float dtv = sDT[tl][ch];
            float xv  = sX [tl][ch];
            float Bv  = sBC[tl][n];
            float Cv  = sBC[tl][16 + n];
            float e   = __expf(a * dtv);
            h = fmaf(e, h, dtv * xv * Bv);
            float p = h * Cv;
            p += __shfl_xor_sync(0xffffffffu, p, 1);
            p += __shfl_xor_sync(0xffffffffu, p, 2);
            p += __shfl_xor_sync(0xffffffffu, p, 4);
            p += __shfl_xor_sync(0xffffffffu, p, 8);
            if (n == 0) {
                sY[tl][ch] = fmaf(Dd, xv, p) * sZ[tl][ch];
            }
        }
        __syncthreads();

        #pragma unroll
        for (int i = 0; i < 4; i++) {
            int j  = tid + i * 512;
            int tl = j >> 5, dd = j & 31;
            y[(rowbase + t0 + tl) * DINNER + d0 + dd] = sY[tl][dd];
        }
    }
}

// ---------------- launch ----------------
extern "C" void kernel_launch(void* const* d_in, const int* in_sizes, int n_in,
                              void* d_out, int out_size)
{
    const float* hidden    = (const float*)d_in[0];
    const float* in_proj_w = (const float*)d_in[1];
    const float* conv_w    = (const float*)d_in[2];
    const float* conv_b    = (const float*)d_in[3];
    const float* x_proj_w  = (const float*)d_in[4];
    const float* dt_proj_w = (const float*)d_in[5];
    const float* dt_proj_b = (const float*)d_in[6];
    const float* A_log     = (const float*)d_in[7];
    const float* Dw        = (const float*)d_in[8];
    const float* out_proj_w= (const float*)d_in[9];
    float* out = (float*)d_out;

    float *p_xz, *p_x, *p_zs, *p_xdbl, *p_dt, *p_y;
    cudaGetSymbolAddress((void**)&p_xz,   g_xz);
    cudaGetSymbolAddress((void**)&p_x,    g_x);
    cudaGetSymbolAddress((void**)&p_zs,   g_zs);
    cudaGetSymbolAddress((void**)&p_xdbl, g_xdbl);
    cudaGetSymbolAddress((void**)&p_dt,   g_dt);
    cudaGetSymbolAddress((void**)&p_y,    g_y);

    dim3 blk(256);

    // 1) xz = hidden @ in_proj_w   (8192 x 4096, K=1024), tf32
    gemm_tf32<false, 0><<<dim3(4096 / 128, NROWS / 128), blk>>>(
        hidden, in_proj_w, nullptr, p_xz, NROWS, 4096, DMODEL, DMODEL, 4096, 4096);

    // 2) conv + silu on x; silu(z)
    conv_silu_kernel<<<(NROWS * DINNER) / 256, 256>>>(p_xz, conv_w, conv_b, p_x, p_zs);

    // 3) x_dbl = x @ x_proj_w (N=96, K=2048), 3xTF32 precise
    gemm_tf32<true, 0><<<dim3(1, NROWS / 128), blk>>>(
        p_x, x_proj_w, nullptr, p_xdbl, NROWS, 96, DINNER, DINNER, 96, 96);

    // 4) dt = softplus(x_dbl[:, :64] @ dt_proj_w + b) (N=2048, K=64), 3xTF32 precise
    gemm_tf32<true, 1><<<dim3(DINNER / 128, NROWS / 128), blk>>>(
        p_xdbl, dt_proj_w, dt_proj_b, p_dt, NROWS, DINNER, DTRANK, 96, DINNER, DINNER);

    // 5) selective scan -> y (already multiplied by silu(z))
    scan_kernel<<<dim3(64, BATCHN), 512>>>(p_xdbl, p_x, p_dt, p_zs, A_log, Dw, p_y);

    // 6) out = y @ out_proj_w (N=1024, K=2048), tf32
    gemm_tf32<false, 0><<<dim3(DMODEL / 128, NROWS / 128), blk>>>(
        p_y, out_proj_w, nullptr, out, NROWS, DMODEL, DINNER, DINNER, DMODEL, DMODEL);
}

// round 2
// speedup vs baseline: 1.2025x; 1.2025x over previous
#include <cuda_runtime.h>
#include <cstdint>

#define BATCHN 4
#define SEQLEN 2048
#define DMODEL 1024
#define DINNER 2048
#define DSTATE 16
#define DTRANK 64
#define NROWS (BATCHN*SEQLEN)   /* 8192 */

// ---------------- scratch (static device globals; no allocations) ----------------
__device__ float g_xz  [NROWS*4096];    // in_proj output (x | z)
__device__ float g_x   [NROWS*DINNER];  // conv+silu output
__device__ float g_zs  [NROWS*DINNER];  // silu(z)
__device__ float g_xdbl[NROWS*96];      // x @ x_proj_w  (dt_in | B | C)
__device__ float g_dt  [NROWS*DINNER];  // softplus(dt_in @ dt_proj_w + b)
__device__ float g_y   [NROWS*DINNER];  // scan output * silu(z)

// ---------------- helpers ----------------
__device__ __forceinline__ float to_tf32(float x) {
    uint32_t u;
    asm("cvt.rna.tf32.f32 %0, %1;" : "=r"(u) : "f"(x));
    return __uint_as_float(u);
}
__device__ __forceinline__ uint32_t to_tf32_u(float x) {
    uint32_t u;
    asm("cvt.rna.tf32.f32 %0, %1;" : "=r"(u) : "f"(x));
    return u;
}

__device__ __forceinline__ void mma8(float* d, const uint32_t* a, const uint32_t* b) {
    asm volatile(
        "mma.sync.aligned.m16n8k8.row.col.f32.tf32.tf32.f32 "
        "{%0,%1,%2,%3}, {%4,%5,%6,%7}, {%8,%9}, {%0,%1,%2,%3};\n"
        : "+f"(d[0]), "+f"(d[1]), "+f"(d[2]), "+f"(d[3])
        : "r"(a[0]), "r"(a[1]), "r"(a[2]), "r"(a[3]), "r"(b[0]), "r"(b[1]));
}

__device__ __forceinline__ void cp_async16(void* smem, const void* gmem) {
    uint32_t s = (uint32_t)__cvta_generic_to_shared(smem);
    asm volatile("cp.async.cg.shared.global [%0], [%1], 16;" :: "r"(s), "l"(gmem));
}

__device__ __forceinline__ float softplusf(float v) {
    return fmaxf(v, 0.f) + log1pf(__expf(-fabsf(v)));
}

// ================= pipelined tf32 GEMM (no bounds checks; M,N mult of 128, K mult of 16) =================
// BM=128, BN=128, BK=16, 2-stage cp.async double buffer, 256 threads, 2 CTAs/SM.
#define A_STRIDE 20   /* 16 + 4 pad, keeps 16B alignment, conflict-free frag reads */
#define B_STRIDE 132

__global__ void __launch_bounds__(256, 2) gemm_tf32_pipe(
    const float* __restrict__ A, const float* __restrict__ B, float* __restrict__ C,
    int K, int lda, int ldb, int ldc)
{
    __shared__ float As[2][128 * A_STRIDE];
    __shared__ float Bs[2][16 * B_STRIDE];

    const int tid  = threadIdx.x;
    const int lane = tid & 31;
    const int w    = tid >> 5;
    const int wr   = w >> 2;       // 0..1
    const int wc   = w & 3;        // 0..3
    const int tig  = lane & 3;
    const int g    = lane >> 2;
    const int m0   = blockIdx.y * 128;
    const int n0   = blockIdx.x * 128;

    // per-thread copy coords
    const int ar  = tid >> 1;            // 0..127 (2 float4 per row handled via i loop)
    const int ac  = (tid & 1) * 2;       // 0 or 2 -> covers c4 {0,1} and {2,3}
    const int br  = tid >> 5;            // 0..7 / +8
    const int bc  = (tid & 31) * 4;      // 0..124

    float acc[4][4][4];
    #pragma unroll
    for (int i = 0; i < 4; i++)
        #pragma unroll
        for (int j = 0; j < 4; j++)
            #pragma unroll
            for (int q = 0; q < 4; q++) acc[i][j][q] = 0.f;

    auto issue_tile = [&](int st, int k0) {
        // A tile: 128 x 16 row-major, stride A_STRIDE
        #pragma unroll
        for (int i = 0; i < 2; i++) {
            cp_async16(&As[st][ar * A_STRIDE + (ac + i) * 4],
                       A + (size_t)(m0 + ar) * lda + k0 + (ac + i) * 4);
        }
        // B tile: 16 x 128 row-major, stride B_STRIDE
        #pragma unroll
        for (int i = 0; i < 2; i++) {
            cp_async16(&Bs[st][(br + i * 8) * B_STRIDE + bc],
                       B + (size_t)(k0 + br + i * 8) * ldb + n0 + bc);
        }
        asm volatile("cp.async.commit_group;");
    };

    const int nk = K >> 4;
    issue_tile(0, 0);

    for (int kt = 0; kt < nk; kt++) {
        if (kt + 1 < nk) {
            issue_tile((kt + 1) & 1, (kt + 1) << 4);
            asm volatile("cp.async.wait_group 1;");
        } else {
            asm volatile("cp.async.wait_group 0;");
        }
        __syncthreads();

        const float* as = As[kt & 1];
        const float* bs = Bs[kt & 1];

        #pragma unroll
        for (int kk = 0; kk < 16; kk += 8) {
            uint32_t ah[4][4], bh[4][2];
            #pragma unroll
            for (int mf = 0; mf < 4; mf++) {
                int mr = wr * 64 + mf * 16 + g;
                ah[mf][0] = to_tf32_u(as[(size_t)mr       * A_STRIDE + kk +     tig]);
                ah[mf][1] = to_tf32_u(as[(size_t)(mr + 8) * A_STRIDE + kk +     tig]);
                ah[mf][2] = to_tf32_u(as[(size_t)mr       * A_STRIDE + kk + 4 + tig]);
                ah[mf][3] = to_tf32_u(as[(size_t)(mr + 8) * A_STRIDE + kk + 4 + tig]);
            }
            #pragma unroll
            for (int nf = 0; nf < 4; nf++) {
                int nc = wc * 32 + nf * 8 + g;
                bh[nf][0] = to_tf32_u(bs[(size_t)(kk +     tig) * B_STRIDE + nc]);
                bh[nf][1] = to_tf32_u(bs[(size_t)(kk + 4 + tig) * B_STRIDE + nc]);
            }
            #pragma unroll
            for (int mf = 0; mf < 4; mf++)
                #pragma unroll
                for (int nf = 0; nf < 4; nf++)
                    mma8(acc[mf][nf], ah[mf], bh[nf]);
        }
        __syncthreads();
    }

    // ---- epilogue ----
    #pragma unroll
    for (int mf = 0; mf < 4; mf++) {
        int row = m0 + wr * 64 + mf * 16 + g;
        #pragma unroll
        for (int nf = 0; nf < 4; nf++) {
            int col = n0 + wc * 32 + nf * 8 + 2 * tig;
            float* cp  = C + (size_t)row * ldc + col;
            float* cp2 = cp + (size_t)8 * ldc;
            cp [0] = acc[mf][nf][0]; cp [1] = acc[mf][nf][1];
            cp2[0] = acc[mf][nf][2]; cp2[1] = acc[mf][nf][3];
        }
    }
}

// ================= original (split-capable) tf32 GEMM for small layers =================
// BM=128, BN=128, BK=16, 256 threads. SPLIT: 3xTF32. EPI: 1 = softplus(v + bias[col])
template<bool SPLIT, int EPI>
__global__ void __launch_bounds__(256) gemm_tf32(
    const float* __restrict__ A, const float* __restrict__ B,
    const float* __restrict__ bias, float* __restrict__ C,
    int M, int N, int K, int lda, int ldb, int ldc)
{
    __shared__ float As [16][132];
    __shared__ float Bs [16][132];
    __shared__ float Asl[SPLIT ? 16 : 1][SPLIT ? 132 : 1];
    __shared__ float Bsl[SPLIT ? 16 : 1][SPLIT ? 132 : 1];

    const int tid  = threadIdx.x;
    const int lane = tid & 31;
    const int w    = tid >> 5;
    const int wr   = w >> 2;
    const int wc   = w & 3;
    const int tig  = lane & 3;
    const int g    = lane >> 2;
    const int m0   = blockIdx.y * 128;
    const int n0   = blockIdx.x * 128;

    float acc[4][4][4];
    #pragma unroll
    for (int i = 0; i < 4; i++)
        #pragma unroll
        for (int j = 0; j < 4; j++)
            #pragma unroll
            for (int q = 0; q < 4; q++) acc[i][j][q] = 0.f;

    for (int k0 = 0; k0 < K; k0 += 16) {
        __syncthreads();
        #pragma unroll
        for (int i = 0; i < 2; i++) {
            int j  = tid + i * 256;
            int r  = j >> 2;
            int c4 = j & 3;
            float4 v = *reinterpret_cast<const float4*>(A + (size_t)(m0 + r) * lda + k0 + c4 * 4);
            float h0 = to_tf32(v.x), h1 = to_tf32(v.y), h2 = to_tf32(v.z), h3 = to_tf32(v.w);
            As[c4*4+0][r] = h0; As[c4*4+1][r] = h1;
            As[c4*4+2][r] = h2; As[c4*4+3][r] = h3;
            if constexpr (SPLIT) {
                Asl[c4*4+0][r] = to_tf32(v.x - h0);
                Asl[c4*4+1][r] = to_tf32(v.y - h1);
                Asl[c4*4+2][r] = to_tf32(v.z - h2);
                Asl[c4*4+3][r] = to_tf32(v.w - h3);
            }
        }
        #pragma unroll
        for (int i = 0; i < 2; i++) {
            int j  = tid + i * 256;
            int r  = j >> 5;
            int c4 = j & 31;
            int n  = n0 + c4 * 4;
            float4 v;
            if (n + 3 < N) {
                v = *reinterpret_cast<const float4*>(B + (size_t)(k0 + r) * ldb + n);
            } else {
                const float* bp = B + (size_t)(k0 + r) * ldb;
                v.x = (n + 0 < N) ? bp[n + 0] : 0.f;
                v.y = (n + 1 < N) ? bp[n + 1] : 0.f;
                v.z = (n + 2 < N) ? bp[n + 2] : 0.f;
                v.w = (n + 3 < N) ? bp[n + 3] : 0.f;
            }
            float h0 = to_tf32(v.x), h1 = to_tf32(v.y), h2 = to_tf32(v.z), h3 = to_tf32(v.w);
            Bs[r][c4*4+0] = h0; Bs[r][c4*4+1] = h1;
            Bs[r][c4*4+2] = h2; Bs[r][c4*4+3] = h3;
            if constexpr (SPLIT) {
                Bsl[r][c4*4+0] = to_tf32(v.x - h0);
                Bsl[r][c4*4+1] = to_tf32(v.y - h1);
                Bsl[r][c4*4+2] = to_tf32(v.z - h2);
                Bsl[r][c4*4+3] = to_tf32(v.w - h3);
            }
        }
        __syncthreads();

        #pragma unroll
        for (int kk = 0; kk < 16; kk += 8) {
            uint32_t ah[4][4], bh[4][2];
            uint32_t al[4][4], bl[4][2];
            #pragma unroll
            for (int mf = 0; mf < 4; mf++) {
                int mr = wr * 64 + mf * 16 + g;
                ah[mf][0] = __float_as_uint(As[kk +     tig][mr    ]);
                ah[mf][1] = __float_as_uint(As[kk +     tig][mr + 8]);
                ah[mf][2] = __float_as_uint(As[kk + 4 + tig][mr    ]);
                ah[mf][3] = __float_as_uint(As[kk + 4 + tig][mr + 8]);
                if constexpr (SPLIT) {
                    al[mf][0] = __float_as_uint(Asl[kk +     tig][mr    ]);
                    al[mf][1] = __float_as_uint(Asl[kk +     tig][mr + 8]);
                    al[mf][2] = __float_as_uint(Asl[kk + 4 + tig][mr    ]);
                    al[mf][3] = __float_as_uint(Asl[kk + 4 + tig][mr + 8]);
                }
            }
            #pragma unroll
            for (int nf = 0; nf < 4; nf++) {
                int nc = wc * 32 + nf * 8 + g;
                bh[nf][0] = __float_as_uint(Bs[kk +     tig][nc]);
                bh[nf][1] = __float_as_uint(Bs[kk + 4 + tig][nc]);
                if constexpr (SPLIT) {
                    bl[nf][0] = __float_as_uint(Bsl[kk +     tig][nc]);
                    bl[nf][1] = __float_as_uint(Bsl[kk + 4 + tig][nc]);
                }
            }
            #pragma unroll
            for (int mf = 0; mf < 4; mf++)
                #pragma unroll
                for (int nf = 0; nf < 4; nf++) {
                    mma8(acc[mf][nf], ah[mf], bh[nf]);
                    if constexpr (SPLIT) {
                        mma8(acc[mf][nf], ah[mf], bl[nf]);
                        mma8(acc[mf][nf], al[mf], bh[nf]);
                    }
                }
        }
    }

    #pragma unroll
    for (int mf = 0; mf < 4; mf++) {
        int row = m0 + wr * 64 + mf * 16 + g;
        #pragma unroll
        for (int nf = 0; nf < 4; nf++) {
            int col = n0 + wc * 32 + nf * 8 + 2 * tig;
            float v0 = acc[mf][nf][0], v1 = acc[mf][nf][1];
            float v2 = acc[mf][nf][2], v3 = acc[mf][nf][3];
            if (EPI == 1) {
                if (col < N)     { float bb = bias[col];     v0 = softplusf(v0 + bb); v2 = softplusf(v2 + bb); }
                if (col + 1 < N) { float bb = bias[col + 1]; v1 = softplusf(v1 + bb); v3 = softplusf(v3 + bb); }
            }
            float* cp  = C + (size_t)row * ldc + col;
            float* cp2 = cp + (size_t)8 * ldc;
            if (col < N)     { cp[0] = v0; cp2[0] = v2; }
            if (col + 1 < N) { cp[1] = v1; cp2[1] = v3; }
        }
    }
}

// ---------------- causal depthwise conv (K=4) + silu, plus silu(z) ----------------
__global__ void conv_silu_kernel(const float* __restrict__ xz,
                                 const float* __restrict__ cw,
                                 const float* __restrict__ cb,
                                 float* __restrict__ xo,
                                 float* __restrict__ zso)
{
    int idx = blockIdx.x * 256 + threadIdx.x;
    int d   = idx & (DINNER - 1);
    int row = idx >> 11;
    int t   = row & (SEQLEN - 1);

    float w0 = cw[d*4+0], w1 = cw[d*4+1], w2 = cw[d*4+2], w3 = cw[d*4+3];
    size_t base = (size_t)row * 4096 + d;
    float acc = cb[d] + xz[base] * w3;
    if (t >= 1) acc = fmaf(xz[base - 4096],     w2, acc);
    if (t >= 2) acc = fmaf(xz[base - 2 * 4096], w1, acc);
    if (t >= 3) acc = fmaf(xz[base - 3 * 4096], w0, acc);
    xo[idx] = acc * (1.f / (1.f + __expf(-acc)));

    float zv = xz[(size_t)row * 4096 + DINNER + d];
    zso[idx] = zv * (1.f / (1.f + __expf(-zv)));
}

// ---------------- selective scan ----------------
__global__ void __launch_bounds__(512) scan_kernel(
    const float* __restrict__ xdbl, const float* __restrict__ xs,
    const float* __restrict__ dts,  const float* __restrict__ zss,
    const float* __restrict__ A_log, const float* __restrict__ Dp,
    float* __restrict__ y)
{
    const int b   = blockIdx.y;
    const int d0  = blockIdx.x * 32;
    const int tid = threadIdx.x;
    const int n   = tid & 15;
    const int ch  = tid >> 4;
    const int d   = d0 + ch;

    __shared__ float sBC[64][32];
    __shared__ float sX [64][32];
    __shared__ float sDT[64][32];
    __shared__ float sZ [64][32];
    __shared__ float sY [64][32];

    const float a  = -__expf(A_log[d * DSTATE + n]);
    const float Dd = Dp[d];
    float h = 0.f;

    const size_t rowbase = (size_t)b * SEQLEN;
    for (int t0 = 0; t0 < SEQLEN; t0 += 64) {
        __syncthreads();
        #pragma unroll
        for (int i = 0; i < 4; i++) {
            int j  = tid + i * 512;
            int tl = j >> 5, dd = j & 31;
            size_t r = rowbase + t0 + tl;
            sX [tl][dd] = xs [r * DINNER + d0 + dd];
            sDT[tl][dd] = dts[r * DINNER + d0 + dd];
            sZ [tl][dd] = zss[r * DINNER + d0 + dd];
            sBC[tl][dd] = xdbl[r * 96 + DTRANK + dd];
        }
        __syncthreads();

        #pragma unroll 4
        for (int tl = 0; tl < 64; tl++) {
            float dtv = sDT[tl][ch];
            float xv  = sX [tl][ch];
            float Bv  = sBC[tl][n];
            float Cv  = sBC[tl][16 + n];
            float e   = __expf(a * dtv);
            h = fmaf(e, h, dtv * xv * Bv);
            float p = h * Cv;
            p += __shfl_xor_sync(0xffffffffu, p, 1);
            p += __shfl_xor_sync(0xffffffffu, p, 2);
            p += __shfl_xor_sync(0xffffffffu, p, 4);
            p += __shfl_xor_sync(0xffffffffu, p, 8);
            if (n == 0) {
                sY[tl][ch] = fmaf(Dd, xv, p) * sZ[tl][ch];
            }
        }
        __syncthreads();

        #pragma unroll
        for (int i = 0; i < 4; i++) {
            int j  = tid + i * 512;
            int tl = j >> 5, dd = j & 31;
            y[(rowbase + t0 + tl) * DINNER + d0 + dd] = sY[tl][dd];
        }
    }
}

// ---------------- launch ----------------
extern "C" void kernel_launch(void* const* d_in, const int* in_sizes, int n_in,
                              void* d_out, int out_size)
{
    const float* hidden    = (const float*)d_in[0];
    const float* in_proj_w = (const float*)d_in[1];
    const float* conv_w    = (const float*)d_in[2];
    const float* conv_b    = (const float*)d_in[3];
    const float* x_proj_w  = (const float*)d_in[4];
    const float* dt_proj_w = (const float*)d_in[5];
    const float* dt_proj_b = (const float*)d_in[6];
    const float* A_log     = (const float*)d_in[7];
    const float* Dw        = (const float*)d_in[8];
    const float* out_proj_w= (const float*)d_in[9];
    float* out = (float*)d_out;

    float *p_xz, *p_x, *p_zs, *p_xdbl, *p_dt, *p_y;
    cudaGetSymbolAddress((void**)&p_xz,   g_xz);
    cudaGetSymbolAddress((void**)&p_x,    g_x);
    cudaGetSymbolAddress((void**)&p_zs,   g_zs);
    cudaGetSymbolAddress((void**)&p_xdbl, g_xdbl);
    cudaGetSymbolAddress((void**)&p_dt,   g_dt);
    cudaGetSymbolAddress((void**)&p_y,    g_y);

    dim3 blk(256);

    // 1) xz = hidden @ in_proj_w   (8192 x 4096, K=1024), tf32 pipelined
    gemm_tf32_pipe<<<dim3(4096 / 128, NROWS / 128), blk>>>(
        hidden, in_proj_w, p_xz, DMODEL, DMODEL, 4096, 4096);

    // 2) conv + silu on x; silu(z)
    conv_silu_kernel<<<(NROWS * DINNER) / 256, 256>>>(p_xz, conv_w, conv_b, p_x, p_zs);

    // 3) x_dbl = x @ x_proj_w (N=96, K=2048), 3xTF32 precise
    gemm_tf32<true, 0><<<dim3(1, NROWS / 128), blk>>>(
        p_x, x_proj_w, nullptr, p_xdbl, NROWS, 96, DINNER, DINNER, 96, 96);

    // 4) dt = softplus(x_dbl[:, :64] @ dt_proj_w + b) (N=2048, K=64), 3xTF32 precise
    gemm_tf32<true, 1><<<dim3(DINNER / 128, NROWS / 128), blk>>>(
        p_xdbl, dt_proj_w, dt_proj_b, p_dt, NROWS, DINNER, DTRANK, 96, DINNER, DINNER);

    // 5) selective scan -> y (already multiplied by silu(z))
    scan_kernel<<<dim3(64, BATCHN), 512>>>(p_xdbl, p_x, p_dt, p_zs, A_log, Dw, p_y);

    // 6) out = y @ out_proj_w (N=1024, K=2048), tf32 pipelined
    gemm_tf32_pipe<<<dim3(DMODEL / 128, NROWS / 128), blk>>>(
        p_y, out_proj_w, out, DINNER, DINNER, DMODEL, DMODEL);
}

// round 4
// speedup vs baseline: 1.2258x; 1.0193x over previous
#include <cuda_runtime.h>
#include <cstdint>

#define BATCHN 4
#define SEQLEN 2048
#define DMODEL 1024
#define DINNER 2048
#define DSTATE 16
#define DTRANK 64
#define NROWS (BATCHN*SEQLEN)   /* 8192 */

// ---------------- scratch (static device globals; no allocations) ----------------
__device__ float g_xz  [NROWS*4096];    // in_proj output (x | z)
__device__ float g_x   [NROWS*DINNER];  // conv+silu output
__device__ float g_zs  [NROWS*DINNER];  // silu(z)
__device__ float g_xdbl[NROWS*96];      // x @ x_proj_w  (dt_in | B | C)
__device__ float g_dt  [NROWS*DINNER];  // softplus(dt_in @ dt_proj_w + b)
__device__ float g_y   [NROWS*DINNER];  // scan output * silu(z), tf32-rounded + k-perm
__device__ float g_hidr[NROWS*DMODEL];  // hidden, tf32-rounded + k-perm
__device__ float g_w1t [4096*DMODEL];   // in_proj_w^T, tf32-rounded + k-perm
__device__ float g_w2t [DMODEL*DINNER]; // out_proj_w^T, tf32-rounded + k-perm

// ---------------- helpers ----------------
__device__ __forceinline__ float to_tf32(float x) {
    uint32_t u;
    asm("cvt.rna.tf32.f32 %0, %1;" : "=r"(u) : "f"(x));
    return __uint_as_float(u);
}

// permute k within groups of 8 so (k, k+4) become adjacent storage columns
__device__ __forceinline__ int kperm(int k) {
    return (k & ~7) | (((k & 3) << 1) | ((k >> 2) & 1));
}

__device__ __forceinline__ void mma8(float* d, const uint32_t* a, const uint32_t* b) {
    asm volatile(
        "mma.sync.aligned.m16n8k8.row.col.f32.tf32.tf32.f32 "
        "{%0,%1,%2,%3}, {%4,%5,%6,%7}, {%8,%9}, {%0,%1,%2,%3};\n"
        : "+f"(d[0]), "+f"(d[1]), "+f"(d[2]), "+f"(d[3])
        : "r"(a[0]), "r"(a[1]), "r"(a[2]), "r"(a[3]), "r"(b[0]), "r"(b[1]));
}

__device__ __forceinline__ void cp_async16(uint32_t smem_addr, const void* gmem) {
    asm volatile("cp.async.cg.shared.global [%0], [%1], 16;" :: "r"(smem_addr), "l"(gmem));
}

__device__ __forceinline__ float softplusf(float v) {
    return fmaxf(v, 0.f) + log1pf(__expf(-fabsf(v)));
}

// ================= HMMA v2: C[M,*] = A[M,K] @ BT[N,K]^T =================
// BM=128, BN=128, BK=16, 3-stage cp.async, 256 threads (8 warps 2x4, warp 64x32).
// A and BT must be tf32-pre-rounded with k-permuted columns. No bounds checks:
// M,N multiples of 128, K multiple of 16.
#define HV_STRIDE 24                       /* words per SMEM row (16 + 8 pad) */
#define HV_STAGE  (2 * 128 * HV_STRIDE)    /* 6144 words per stage (A then B) */
#define HV_SMEM_BYTES (3 * HV_STAGE * 4)   /* 73728 */

__global__ void __launch_bounds__(256, 2) gemm_hmma_v2(
    const float* __restrict__ A, const float* __restrict__ BT, float* __restrict__ C,
    int K, int ldc)
{
    extern __shared__ float sm[];
    const uint32_t sb = (uint32_t)__cvta_generic_to_shared(sm);

    const int tid  = threadIdx.x;
    const int lane = tid & 31;
    const int w    = tid >> 5;
    const int wr   = w >> 2;       // 0..1
    const int wc   = w & 3;        // 0..3
    const int tig  = lane & 3;
    const int g    = lane >> 2;
    const int m0   = blockIdx.y * 128;
    const int n0   = blockIdx.x * 128;

    const int r_cp   = tid >> 2;         // 0..63 -> +64 on second iter
    const int seg_cp = (tid & 3) * 4;    // word offset 0,4,8,12

    float acc[4][4][4];
    #pragma unroll
    for (int i = 0; i < 4; i++)
        #pragma unroll
        for (int j = 0; j < 4; j++)
            #pragma unroll
            for (int q = 0; q < 4; q++) acc[i][j][q] = 0.f;

    auto issue = [&](int c, int s) {
        const float* Ab = A + (size_t)m0 * K + c * 16;
        const float* Bb = BT + (size_t)n0 * K + c * 16;
        #pragma unroll
        for (int i = 0; i < 2; i++) {
            int r = r_cp + i * 64;
            cp_async16(sb + (uint32_t)(s * HV_STAGE + r * HV_STRIDE + seg_cp) * 4,
                       Ab + (size_t)r * K + seg_cp);
            cp_async16(sb + (uint32_t)(s * HV_STAGE + 128 * HV_STRIDE + r * HV_STRIDE + seg_cp) * 4,
                       Bb + (size_t)r * K + seg_cp);
        }
        asm volatile("cp.async.commit_group;");
    };

    const int nc = K >> 4;
    issue(0, 0);
    if (nc > 1) issue(1, 1);

    for (int c = 0; c < nc; c++) {
        const int s = c % 3;
        if (c + 2 < nc) {
            issue(c + 2, (c + 2) % 3);
            asm volatile("cp.async.wait_group 2;");
        } else if (c + 1 < nc) {
            asm volatile("cp.async.wait_group 1;");
        } else {
            asm volatile("cp.async.wait_group 0;");
        }
        __syncthreads();

        const float* as = sm + s * HV_STAGE;
        const float* bs = as + 128 * HV_STRIDE;

        #pragma unroll
        for (int kk = 0; kk < 16; kk += 8) {
            uint32_t ah[4][4], bh[4][2];
            #pragma unroll
            for (int mf = 0; mf < 4; mf++) {
                int mr = wr * 64 + mf * 16 + g;
                uint2 p = *reinterpret_cast<const uint2*>(as + mr * HV_STRIDE + kk + 2 * tig);
                uint2 q = *reinterpret_cast<const uint2*>(as + (mr + 8) * HV_STRIDE + kk + 2 * tig);
                ah[mf][0] = p.x; ah[mf][1] = q.x; ah[mf][2] = p.y; ah[mf][3] = q.y;
            }
            #pragma unroll
            for (int nf = 0; nf < 4; nf++) {
                int ncol = wc * 32 + nf * 8 + g;
                uint2 b = *reinterpret_cast<const uint2*>(bs + ncol * HV_STRIDE + kk + 2 * tig);
                bh[nf][0] = b.x; bh[nf][1] = b.y;
            }
            #pragma unroll
            for (int mf = 0; mf < 4; mf++)
                #pragma unroll
                for (int nf = 0; nf < 4; nf++)
                    mma8(acc[mf][nf], ah[mf], bh[nf]);
        }
        __syncthreads();
    }

    // ---- epilogue ----
    #pragma unroll
    for (int mf = 0; mf < 4; mf++) {
        int row = m0 + wr * 64 + mf * 16 + g;
        #pragma unroll
        for (int nf = 0; nf < 4; nf++) {
            int col = n0 + wc * 32 + nf * 8 + 2 * tig;
            float* cp  = C + (size_t)row * ldc + col;
            float* cp2 = cp + (size_t)8 * ldc;
            cp [0] = acc[mf][nf][0]; cp [1] = acc[mf][nf][1];
            cp2[0] = acc[mf][nf][2]; cp2[1] = acc[mf][nf][3];
        }
    }
}

// ---------------- tf32 round + k-perm (for hidden) ----------------
__global__ void round_perm_kernel(const float* __restrict__ in, float* __restrict__ out, int n)
{
    int i = blockIdx.x * 256 + threadIdx.x;
    if (i < n) {
        int dst = (i & ~7) | (((i & 3) << 1) | ((i >> 2) & 1));
        out[dst] = to_tf32(in[i]);
    }
}

// ---------------- transpose + tf32 round + k-perm: WT[n][kperm(k)] = rna(W[k][n]) ----------------
__global__ void transpose_round_kernel(const float* __restrict__ W, float* __restrict__ WT,
                                       int K, int N)
{
    __shared__ float t[32][33];
    const int n0 = blockIdx.x * 32;
    const int k0 = blockIdx.y * 32;
    const int tx = threadIdx.x, ty = threadIdx.y;
    #pragma unroll
    for (int i = 0; i < 4; i++)
        t[ty + i * 8][tx] = W[(size_t)(k0 + ty + i * 8) * N + n0 + tx];
    __syncthreads();
    #pragma unroll
    for (int i = 0; i < 4; i++)
        WT[(size_t)(n0 + ty + i * 8) * K + k0 + kperm(tx)] = to_tf32(t[tx][ty + i * 8]);
}

// ================= split-capable tf32 GEMM for small layers (3xTF32) =================
template<bool SPLIT, int EPI>
__global__ void __launch_bounds__(256) gemm_tf32(
    const float* __restrict__ A, const float* __restrict__ B,
    const float* __restrict__ bias, float* __restrict__ C,
    int M, int N, int K, int lda, int ldb, int ldc)
{
    __shared__ float As [16][132];
    __shared__ float Bs [16][132];
    __shared__ float Asl[SPLIT ? 16 : 1][SPLIT ? 132 : 1];
    __shared__ float Bsl[SPLIT ? 16 : 1][SPLIT ? 132 : 1];

    const int tid  = threadIdx.x;
    const int lane = tid & 31;
    const int w    = tid >> 5;
    const int wr   = w >> 2;
    const int wc   = w & 3;
    const int tig  = lane & 3;
    const int g    = lane >> 2;
    const int m0   = blockIdx.y * 128;
    const int n0   = blockIdx.x * 128;

    float acc[4][4][4];
    #pragma unroll
    for (int i = 0; i < 4; i++)
        #pragma unroll
        for (int j = 0; j < 4; j++)
            #pragma unroll
            for (int q = 0; q < 4; q++) acc[i][j][q] = 0.f;

    for (int k0 = 0; k0 < K; k0 += 16) {
        __syncthreads();
        #pragma unroll
        for (int i = 0; i < 2; i++) {
            int j  = tid + i * 256;
            int r  = j >> 2;
            int c4 = j & 3;
            float4 v = *reinterpret_cast<const float4*>(A + (size_t)(m0 + r) * lda + k0 + c4 * 4);
            float h0 = to_tf32(v.x), h1 = to_tf32(v.y), h2 = to_tf32(v.z), h3 = to_tf32(v.w);
            As[c4*4+0][r] = h0; As[c4*4+1][r] = h1;
            As[c4*4+2][r] = h2; As[c4*4+3][r] = h3;
            if constexpr (SPLIT) {
                Asl[c4*4+0][r] = to_tf32(v.x - h0);
                Asl[c4*4+1][r] = to_tf32(v.y - h1);
                Asl[c4*4+2][r] = to_tf32(v.z - h2);
                Asl[c4*4+3][r] = to_tf32(v.w - h3);
            }
        }
        #pragma unroll
        for (int i = 0; i < 2; i++) {
            int j  = tid + i * 256;
            int r  = j >> 5;
            int c4 = j & 31;
            int n  = n0 + c4 * 4;
            float4 v;
            if (n + 3 < N) {
                v = *reinterpret_cast<const float4*>(B + (size_t)(k0 + r) * ldb + n);
            } else {
                const float* bp = B + (size_t)(k0 + r) * ldb;
                v.x = (n + 0 < N) ? bp[n + 0] : 0.f;
                v.y = (n + 1 < N) ? bp[n + 1] : 0.f;
                v.z = (n + 2 < N) ? bp[n + 2] : 0.f;
                v.w = (n + 3 < N) ? bp[n + 3] : 0.f;
            }
            float h0 = to_tf32(v.x), h1 = to_tf32(v.y), h2 = to_tf32(v.z), h3 = to_tf32(v.w);
            Bs[r][c4*4+0] = h0; Bs[r][c4*4+1] = h1;
            Bs[r][c4*4+2] = h2; Bs[r][c4*4+3] = h3;
            if constexpr (SPLIT) {
                Bsl[r][c4*4+0] = to_tf32(v.x - h0);
                Bsl[r][c4*4+1] = to_tf32(v.y - h1);
                Bsl[r][c4*4+2] = to_tf32(v.z - h2);
                Bsl[r][c4*4+3] = to_tf32(v.w - h3);
            }
        }
        __syncthreads();

        #pragma unroll
        for (int kk = 0; kk < 16; kk += 8) {
            uint32_t ah[4][4], bh[4][2];
            uint32_t al[4][4], bl[4][2];
            #pragma unroll
            for (int mf = 0; mf < 4; mf++) {
                int mr = wr * 64 + mf * 16 + g;
                ah[mf][0] = __float_as_uint(As[kk +     tig][mr    ]);
                ah[mf][1] = __float_as_uint(As[kk +     tig][mr + 8]);
                ah[mf][2] = __float_as_uint(As[kk + 4 + tig][mr    ]);
                ah[mf][3] = __float_as_uint(As[kk + 4 + tig][mr + 8]);
                if constexpr (SPLIT) {
                    al[mf][0] = __float_as_uint(Asl[kk +     tig][mr    ]);
                    al[mf][1] = __float_as_uint(Asl[kk +     tig][mr + 8]);
                    al[mf][2] = __float_as_uint(Asl[kk + 4 + tig][mr    ]);
                    al[mf][3] = __float_as_uint(Asl[kk + 4 + tig][mr + 8]);
                }
            }
            #pragma unroll
            for (int nf = 0; nf < 4; nf++) {
                int nc = wc * 32 + nf * 8 + g;
                bh[nf][0] = __float_as_uint(Bs[kk +     tig][nc]);
                bh[nf][1] = __float_as_uint(Bs[kk + 4 + tig][nc]);
                if constexpr (SPLIT) {
                    bl[nf][0] = __float_as_uint(Bsl[kk +     tig][nc]);
                    bl[nf][1] = __float_as_uint(Bsl[kk + 4 + tig][nc]);
                }
            }
            #pragma unroll
            for (int mf = 0; mf < 4; mf++)
                #pragma unroll
                for (int nf = 0; nf < 4; nf++) {
                    mma8(acc[mf][nf], ah[mf], bh[nf]);
                    if constexpr (SPLIT) {
                        mma8(acc[mf][nf], ah[mf], bl[nf]);
                        mma8(acc[mf][nf], al[mf], bh[nf]);
                    }
                }
        }
    }

    #pragma unroll
    for (int mf = 0; mf < 4; mf++) {
        int row = m0 + wr * 64 + mf * 16 + g;
        #pragma unroll
        for (int nf = 0; nf < 4; nf++) {
            int col = n0 + wc * 32 + nf * 8 + 2 * tig;
            float v0 = acc[mf][nf][0], v1 = acc[mf][nf][1];
            float v2 = acc[mf][nf][2], v3 = acc[mf][nf][3];
            if (EPI == 1) {
                if (col < N)     { float bb = bias[col];     v0 = softplusf(v0 + bb); v2 = softplusf(v2 + bb); }
                if (col + 1 < N) { float bb = bias[col + 1]; v1 = softplusf(v1 + bb); v3 = softplusf(v3 + bb); }
            }
            float* cp  = C + (size_t)row * ldc + col;
            float* cp2 = cp + (size_t)8 * ldc;
            if (col < N)     { cp[0] = v0; cp2[0] = v2; }
            if (col + 1 < N) { cp[1] = v1; cp2[1] = v3; }
        }
    }
}

// ---------------- causal depthwise conv (K=4) + silu, plus silu(z) ----------------
__global__ void conv_silu_kernel(const float* __restrict__ xz,
                                 const float* __restrict__ cw,
                                 const float* __restrict__ cb,
                                 float* __restrict__ xo,
                                 float* __restrict__ zso)
{
    int idx = blockIdx.x * 256 + threadIdx.x;
    int d   = idx & (DINNER - 1);
    int row = idx >> 11;
    int t   = row & (SEQLEN - 1);

    float w0 = cw[d*4+0], w1 = cw[d*4+1], w2 = cw[d*4+2], w3 = cw[d*4+3];
    size_t base = (size_t)row * 4096 + d;
    float acc = cb[d] + xz[base] * w3;
    if (t >= 1) acc = fmaf(xz[base - 4096],     w2, acc);
    if (t >= 2) acc = fmaf(xz[base - 2 * 4096], w1, acc);
    if (t >= 3) acc = fmaf(xz[base - 3 * 4096], w0, acc);
    xo[idx] = acc * (1.f / (1.f + __expf(-acc)));

    float zv = xz[(size_t)row * 4096 + DINNER + d];
    zso[idx] = zv * (1.f / (1.f + __expf(-zv)));
}

// ---------------- selective scan (writes tf32-rounded, k-permuted y) ----------------
__global__ void __launch_bounds__(512) scan_kernel(
    const float* __restrict__ xdbl, const float* __restrict__ xs,
    const float* __restrict__ dts,  const float* __restrict__ zss,
    const float* __restrict__ A_log, const float* __restrict__ Dp,
    float* __restrict__ y)
{
    const int b   = blockIdx.y;
    const int d0  = blockIdx.x * 32;
    const int tid = threadIdx.x;
    const int n   = tid & 15;
    const int ch  = tid >> 4;
    const int d   = d0 + ch;

    __shared__ float sBC[64][32];
    __shared__ float sX [64][32];
    __shared__ float sDT[64][32];
    __shared__ float sZ [64][32];
    __shared__ float sY [64][32];

    const float a  = -__expf(A_log[d * DSTATE + n]);
    const float Dd = Dp[d];
    float h = 0.f;

    const size_t rowbase = (size_t)b * SEQLEN;
    for (int t0 = 0; t0 < SEQLEN; t0 += 64) {
        __syncthreads();
        #pragma unroll
        for (int i = 0; i < 4; i++) {
            int j  = tid + i * 512;
            int tl = j >> 5, dd = j & 31;
            size_t r = rowbase + t0 + tl;
            sX [tl][dd] = xs [r * DINNER + d0 + dd];
            sDT[tl][dd] = dts[r * DINNER + d0 + dd];
            sZ [tl][dd] = zss[r * DINNER + d0 + dd];
            sBC[tl][dd] = xdbl[r * 96 + DTRANK + dd];
        }
        __syncthreads();

        #pragma unroll 4
        for (int tl = 0; tl < 64; tl++) {
            float dtv = sDT[tl][ch];
            float xv  = sX [tl][ch];
            float Bv  = sBC[tl][n];
            float Cv  = sBC[tl][16 + n];
            float e   = __expf(a * dtv);
            h = fmaf(e, h, dtv * xv * Bv);
            float p = h * Cv;
            p += __shfl_xor_sync(0xffffffffu, p, 1);
            p += __shfl_xor_sync(0xffffffffu, p, 2);
            p += __shfl_xor_sync(0xffffffffu, p, 4);
            p += __shfl_xor_sync(0xffffffffu, p, 8);
            if (n == 0) {
                sY[tl][ch] = fmaf(Dd, xv, p) * sZ[tl][ch];
            }
        }
        __syncthreads();

        #pragma unroll
        for (int i = 0; i < 4; i++) {
            int j  = tid + i * 512;
            int tl = j >> 5, dd = j & 31;
            y[(rowbase + t0 + tl) * DINNER + d0 + kperm(dd)] = to_tf32(sY[tl][dd]);
        }
    }
}

// ---------------- launch ----------------
extern "C" void kernel_launch(void* const* d_in, const int* in_sizes, int n_in,
                              void* d_out, int out_size)
{
    const float* hidden    = (const float*)d_in[0];
    const float* in_proj_w = (const float*)d_in[1];
    const float* conv_w    = (const float*)d_in[2];
    const float* conv_b    = (const float*)d_in[3];
    const float* x_proj_w  = (const float*)d_in[4];
    const float* dt_proj_w = (const float*)d_in[5];
    const float* dt_proj_b = (const float*)d_in[6];
    const float* A_log     = (const float*)d_in[7];
    const float* Dw        = (const float*)d_in[8];
    const float* out_proj_w= (const float*)d_in[9];
    float* out = (float*)d_out;

    float *p_xz, *p_x, *p_zs, *p_xdbl, *p_dt, *p_y, *p_hidr, *p_w1t, *p_w2t;
    cudaGetSymbolAddress((void**)&p_xz,   g_xz);
    cudaGetSymbolAddress((void**)&p_x,    g_x);
    cudaGetSymbolAddress((void**)&p_zs,   g_zs);
    cudaGetSymbolAddress((void**)&p_xdbl, g_xdbl);
    cudaGetSymbolAddress((void**)&p_dt,   g_dt);
    cudaGetSymbolAddress((void**)&p_y,    g_y);
    cudaGetSymbolAddress((void**)&p_hidr, g_hidr);
    cudaGetSymbolAddress((void**)&p_w1t,  g_w1t);
    cudaGetSymbolAddress((void**)&p_w2t,  g_w2t);

    cudaFuncSetAttribute(gemm_hmma_v2, cudaFuncAttributeMaxDynamicSharedMemorySize, HV_SMEM_BYTES);

    // 0) pre-round (+k-perm) hidden; transpose+round(+k-perm) weights
    round_perm_kernel<<<(NROWS * DMODEL + 255) / 256, 256>>>(hidden, p_hidr, NROWS * DMODEL);
    transpose_round_kernel<<<dim3(4096 / 32, DMODEL / 32), dim3(32, 8)>>>(in_proj_w, p_w1t, DMODEL, 4096);
    transpose_round_kernel<<<dim3(DMODEL / 32, DINNER / 32), dim3(32, 8)>>>(out_proj_w, p_w2t, DINNER, DMODEL);

    // 1) xz = hidden @ in_proj_w (8192 x 4096, K=1024)
    gemm_hmma_v2<<<dim3(4096 / 128, NROWS / 128), 256, HV_SMEM_BYTES>>>(
        p_hidr, p_w1t, p_xz, DMODEL, 4096);

    // 2) conv + silu on x; silu(z)
    conv_silu_kernel<<<(NROWS * DINNER) / 256, 256>>>(p_xz, conv_w, conv_b, p_x, p_zs);

    // 3) x_dbl = x @ x_proj_w (N=96, K=2048), 3xTF32 precise
    gemm_tf32<true, 0><<<dim3(1, NROWS / 128), 256>>>(
        p_x, x_proj_w, nullptr, p_xdbl, NROWS, 96, DINNER, DINNER, 96, 96);

    // 4) dt = softplus(x_dbl[:, :64] @ dt_proj_w + b) (N=2048, K=64), 3xTF32 precise
    gemm_tf32<true, 1><<<dim3(DINNER / 128, NROWS / 128), 256>>>(
        p_xdbl, dt_proj_w, dt_proj_b, p_dt, NROWS, DINNER, DTRANK, 96, DINNER, DINNER);

    // 5) selective scan -> y (already multiplied by silu(z)), rounded + permuted
    scan_kernel<<<dim3(64, BATCHN), 512>>>(p_xdbl, p_x, p_dt, p_zs, A_log, Dw, p_y);

    // 6) out = y @ out_proj_w (N=1024, K=2048)
    gemm_hmma_v2<<<dim3(DMODEL / 128, NROWS / 128), 256, HV_SMEM_BYTES>>>(
        p_y, p_w2t, out, DINNER, DMODEL);
}

// round 5
// speedup vs baseline: 1.3032x; 1.0632x over previous
#include <cuda_runtime.h>
#include <cstdint>

#define BATCHN 4
#define SEQLEN 2048
#define DMODEL 1024
#define DINNER 2048
#define DSTATE 16
#define DTRANK 64
#define NROWS (BATCHN*SEQLEN)   /* 8192 */

// ---------------- scratch (static device globals; no allocations) ----------------
__device__ float g_xz  [NROWS*4096];     // in_proj output (x | z)
__device__ float g_x   [NROWS*DINNER];   // conv+silu output (fp32, for scan)
__device__ float g_xh  [NROWS*DINNER];   // conv+silu tf32 hi, p16
__device__ float g_xl  [NROWS*DINNER];   // conv+silu tf32 lo, p16
__device__ float g_zs  [NROWS*DINNER];   // silu(z)
__device__ float g_bc  [NROWS*32];       // B|C (fp32), dense
__device__ float g_dth [NROWS*DTRANK];   // dt_in hi, p16
__device__ float g_dtl [NROWS*DTRANK];   // dt_in lo, p16
__device__ float g_dt  [NROWS*DINNER];   // softplus(dt_in @ dt_proj_w + b)
__device__ float g_y   [NROWS*DINNER];   // scan out * silu(z), tf32, p16
__device__ float g_hidr[NROWS*DMODEL];   // hidden, tf32, p16
__device__ float g_w1t [4096*DMODEL];    // in_proj_w^T, tf32, p16
__device__ float g_w2t [DMODEL*DINNER];  // out_proj_w^T, tf32, p16
__device__ float g_xwh [128*DINNER];     // x_proj_w^T hi (rows 96..127 stay zero)
__device__ float g_xwl [128*DINNER];     // x_proj_w^T lo
__device__ float g_dwh [DINNER*DTRANK];  // dt_proj_w^T hi
__device__ float g_dwl [DINNER*DTRANK];  // dt_proj_w^T lo

// ---------------- helpers ----------------
__device__ __forceinline__ float to_tf32(float x) {
    uint32_t u;
    asm("cvt.rna.tf32.f32 %0, %1;" : "=r"(u) : "f"(x));
    return __uint_as_float(u);
}

// permute k within groups of 16: (k,k+4,k+8,k+12) become 4 adjacent words
__device__ __forceinline__ int p16(int k) {
    return (k & ~15) | ((k & 3) << 2) | ((k >> 2) & 3);
}

__device__ __forceinline__ void mma8(float* d, const uint32_t* a, const uint32_t* b) {
    asm volatile(
        "mma.sync.aligned.m16n8k8.row.col.f32.tf32.tf32.f32 "
        "{%0,%1,%2,%3}, {%4,%5,%6,%7}, {%8,%9}, {%0,%1,%2,%3};\n"
        : "+f"(d[0]), "+f"(d[1]), "+f"(d[2]), "+f"(d[3])
        : "r"(a[0]), "r"(a[1]), "r"(a[2]), "r"(a[3]), "r"(b[0]), "r"(b[1]));
}

__device__ __forceinline__ void cp_async16(uint32_t smem_addr, const void* gmem) {
    asm volatile("cp.async.cg.shared.global [%0], [%1], 16;" :: "r"(smem_addr), "l"(gmem));
}

__device__ __forceinline__ float softplus_fast(float v) {
    return fmaxf(v, 0.f) + __logf(1.f + __expf(-fabsf(v)));
}

// ================= big GEMM: 128x256 tile, 4-stage, 1 sync/tile =================
// C[M,*] = A[M,K] @ BT[N,K]^T ; A,BT tf32-pre-rounded, p16-packed. M%128==0, N%256==0, K%16==0.
#define BG_STG (384*16)                 /* words per stage: A 128x16 then B 256x16 */
#define BG_SMEM (4*BG_STG*4)            /* 98304 bytes */

__global__ void __launch_bounds__(256) gemm_big(
    const float* __restrict__ A, const float* __restrict__ BT, float* __restrict__ C,
    int K, int ldc)
{
    extern __shared__ float sm[];
    const uint32_t sb = (uint32_t)__cvta_generic_to_shared(sm);

    const int tid  = threadIdx.x;
    const int lane = tid & 31;
    const int w    = tid >> 5;
    const int wr   = w >> 2;        // 0..1
    const int wc   = w & 3;         // 0..3
    const int tig  = lane & 3;
    const int g    = lane >> 2;
    const int m0   = blockIdx.y * 128;
    const int n0   = blockIdx.x * 256;

    float acc[4][8][4];
    #pragma unroll
    for (int i = 0; i < 4; i++)
        #pragma unroll
        for (int j = 0; j < 8; j++)
            #pragma unroll
            for (int q = 0; q < 4; q++) acc[i][j][q] = 0.f;

    const int nc = K >> 4;

    auto copy = [&](int c, int s) {
        const float* Ab = A + (size_t)m0 * K + c * 16;
        #pragma unroll
        for (int i = 0; i < 2; i++) {
            int idx = tid + i * 256;
            int r = idx >> 2, sg = (idx & 3) * 4;
            cp_async16(sb + (uint32_t)(s * BG_STG + r * 16 + sg) * 4,
                       Ab + (size_t)r * K + sg);
        }
        const float* Bb = BT + (size_t)n0 * K + c * 16;
        #pragma unroll
        for (int i = 0; i < 4; i++) {
            int idx = tid + i * 256;
            int r = idx >> 2, sg = (idx & 3) * 4;
            cp_async16(sb + (uint32_t)(s * BG_STG + 2048 + r * 16 + sg) * 4,
                       Bb + (size_t)r * K + sg);
        }
    };

    #pragma unroll
    for (int p = 0; p < 3; p++) {
        if (p < nc) copy(p, p);
        asm volatile("cp.async.commit_group;");
    }

    for (int c = 0; c < nc; c++) {
        const int s = c & 3;
        asm volatile("cp.async.wait_group 2;");
        __syncthreads();

        const float* as = sm + s * BG_STG;
        const float* bs = as + 2048;

        uint4 av[4][2];
        #pragma unroll
        for (int mf = 0; mf < 4; mf++) {
            int mr = wr * 64 + mf * 16 + g;
            av[mf][0] = *reinterpret_cast<const uint4*>(as + mr * 16 + 4 * tig);
            av[mf][1] = *reinterpret_cast<const uint4*>(as + (mr + 8) * 16 + 4 * tig);
        }
        #pragma unroll
        for (int nh = 0; nh < 2; nh++) {           // process B in halves (reg pressure)
            uint4 bv[4];
            #pragma unroll
            for (int nf = 0; nf < 4; nf++) {
                int ncol = wc * 64 + (nh * 4 + nf) * 8 + g;
                bv[nf] = *reinterpret_cast<const uint4*>(bs + ncol * 16 + 4 * tig);
            }
            #pragma unroll
            for (int mf = 0; mf < 4; mf++) {
                uint32_t a0[4] = {av[mf][0].x, av[mf][1].x, av[mf][0].y, av[mf][1].y};
                uint32_t a8[4] = {av[mf][0].z, av[mf][1].z, av[mf][0].w, av[mf][1].w};
                #pragma unroll
                for (int nf = 0; nf < 4; nf++) {
                    uint32_t b0[2] = {bv[nf].x, bv[nf].y};
                    uint32_t b8[2] = {bv[nf].z, bv[nf].w};
                    mma8(acc[mf][nh * 4 + nf], a0, b0);
                    mma8(acc[mf][nh * 4 + nf], a8, b8);
                }
            }
        }

        if (c + 3 < nc) copy(c + 3, (c + 3) & 3);
        asm volatile("cp.async.commit_group;");
    }

    // ---- epilogue ----
    #pragma unroll
    for (int mf = 0; mf < 4; mf++) {
        int row = m0 + wr * 64 + mf * 16 + g;
        #pragma unroll
        for (int nf = 0; nf < 8; nf++) {
            int col = n0 + wc * 64 + nf * 8 + 2 * tig;
            float* cp  = C + (size_t)row * ldc + col;
            float* cp2 = cp + (size_t)8 * ldc;
            cp [0] = acc[mf][nf][0]; cp [1] = acc[mf][nf][1];
            cp2[0] = acc[mf][nf][2]; cp2[1] = acc[mf][nf][3];
        }
    }
}

// ================= split (3xTF32) GEMM: 128x128 tile, 3-stage =================
// Operands pre-split hi/lo, p16-packed. EPI 1: softplus(v+bias[col]) -> C.
// EPI 2: cols 0..63 -> dt hi/lo (p16); cols 64..95 -> bc dense; cols 96+ dropped.
#define SP_STG (4*128*16)               /* words: Ahi, Alo, Bhi, Blo */
#define SP_SMEM (3*SP_STG*4)            /* 98304 bytes */

template<int EPI>
__global__ void __launch_bounds__(256) gemm_split(
    const float* __restrict__ Ah, const float* __restrict__ Al,
    const float* __restrict__ Bh, const float* __restrict__ Bl,
    const float* __restrict__ bias, float* __restrict__ C,
    float* __restrict__ dth, float* __restrict__ dtl, float* __restrict__ bc,
    int K, int ldc)
{
    extern __shared__ float sm[];
    const uint32_t sb = (uint32_t)__cvta_generic_to_shared(sm);

    const int tid  = threadIdx.x;
    const int lane = tid & 31;
    const int w    = tid >> 5;
    const int wr   = w >> 2;        // 0..1
    const int wc   = w & 3;         // 0..3
    const int tig  = lane & 3;
    const int g    = lane >> 2;
    const int m0   = blockIdx.y * 128;
    const int n0   = blockIdx.x * 128;

    float acc[4][4][4];
    #pragma unroll
    for (int i = 0; i < 4; i++)
        #pragma unroll
        for (int j = 0; j < 4; j++)
            #pragma unroll
            for (int q = 0; q < 4; q++) acc[i][j][q] = 0.f;

    const int nc = K >> 4;

    auto copy = [&](int c, int s) {
        #pragma unroll
        for (int i = 0; i < 2; i++) {
            int idx = tid + i * 256;
            int r = idx >> 2, sg = (idx & 3) * 4;
            size_t go = (size_t)r * K + c * 16 + sg;
            uint32_t so = (uint32_t)(s * SP_STG + r * 16 + sg) * 4;
            cp_async16(sb + so,             Ah + (size_t)m0 * K + go);
            cp_async16(sb + so + 2048 * 4,  Al + (size_t)m0 * K + go);
            cp_async16(sb + so + 4096 * 4,  Bh + (size_t)n0 * K + go);
            cp_async16(sb + so + 6144 * 4,  Bl + (size_t)n0 * K + go);
        }
    };

    #pragma unroll
    for (int p = 0; p < 2; p++) {
        if (p < nc) copy(p, p);
        asm volatile("cp.async.commit_group;");
    }

    int s = 0;
    for (int c = 0; c < nc; c++) {
        asm volatile("cp.async.wait_group 1;");
        __syncthreads();

        const float* ah = sm + s * SP_STG;
        const float* al = ah + 2048;
        const float* bh = ah + 4096;
        const float* bl = ah + 6144;

        uint4 avh[4][2], avl[4][2], bvh[4], bvl[4];
        #pragma unroll
        for (int mf = 0; mf < 4; mf++) {
            int mr = wr * 64 + mf * 16 + g;
            avh[mf][0] = *reinterpret_cast<const uint4*>(ah + mr * 16 + 4 * tig);
            avh[mf][1] = *reinterpret_cast<const uint4*>(ah + (mr + 8) * 16 + 4 * tig);
            avl[mf][0] = *reinterpret_cast<const uint4*>(al + mr * 16 + 4 * tig);
            avl[mf][1] = *reinterpret_cast<const uint4*>(al + (mr + 8) * 16 + 4 * tig);
        }
        #pragma unroll
        for (int nf = 0; nf < 4; nf++) {
            int ncol = wc * 32 + nf * 8 + g;
            bvh[nf] = *reinterpret_cast<const uint4*>(bh + ncol * 16 + 4 * tig);
            bvl[nf] = *reinterpret_cast<const uint4*>(bl + ncol * 16 + 4 * tig);
        }
        #pragma unroll
        for (int mf = 0; mf < 4; mf++) {
            uint32_t ah0[4] = {avh[mf][0].x, avh[mf][1].x, avh[mf][0].y, avh[mf][1].y};
            uint32_t ah8[4] = {avh[mf][0].z, avh[mf][1].z, avh[mf][0].w, avh[mf][1].w};
            uint32_t al0[4] = {avl[mf][0].x, avl[mf][1].x, avl[mf][0].y, avl[mf][1].y};
            uint32_t al8[4] = {avl[mf][0].z, avl[mf][1].z, avl[mf][0].w, avl[mf][1].w};
            #pragma unroll
            for (int nf = 0; nf < 4; nf++) {
                uint32_t bh0[2] = {bvh[nf].x, bvh[nf].y};
                uint32_t bh8[2] = {bvh[nf].z, bvh[nf].w};
                uint32_t bl0[2] = {bvl[nf].x, bvl[nf].y};
                uint32_t bl8[2] = {bvl[nf].z, bvl[nf].w};
                mma8(acc[mf][nf], ah0, bh0);
                mma8(acc[mf][nf], ah0, bl0);
                mma8(acc[mf][nf], al0, bh0);
                mma8(acc[mf][nf], ah8, bh8);
                mma8(acc[mf][nf], ah8, bl8);
                mma8(acc[mf][nf], al8, bh8);
            }
        }

        if (c + 2 < nc) copy(c + 2, (c + 2) % 3);
        asm volatile("cp.async.commit_group;");
        s = (s + 1 == 3) ? 0 : s + 1;
    }

    // ---- epilogue ----
    #pragma unroll
    for (int mf = 0; mf < 4; mf++) {
        int row = m0 + wr * 64 + mf * 16 + g;
        #pragma unroll
        for (int nf = 0; nf < 4; nf++) {
            int col = n0 + wc * 32 + nf * 8 + 2 * tig;
            float v[4] = {acc[mf][nf][0], acc[mf][nf][1], acc[mf][nf][2], acc[mf][nf][3]};
            if (EPI == 1) {
                float b0 = bias[col], b1 = bias[col + 1];
                float* cp  = C + (size_t)row * ldc + col;
                float* cp2 = cp + (size_t)8 * ldc;
                cp [0] = softplus_fast(v[0] + b0); cp [1] = softplus_fast(v[1] + b1);
                cp2[0] = softplus_fast(v[2] + b0); cp2[1] = softplus_fast(v[3] + b1);
            } else { // EPI == 2
                if (col < 64) {
                    int pc0 = p16(col), pc1 = p16(col + 1);
                    float h0 = to_tf32(v[0]), h1 = to_tf32(v[1]);
                    float h2 = to_tf32(v[2]), h3 = to_tf32(v[3]);
                    dth[(size_t)row * 64 + pc0] = h0;       dth[(size_t)row * 64 + pc1] = h1;
                    dth[(size_t)(row + 8) * 64 + pc0] = h2; dth[(size_t)(row + 8) * 64 + pc1] = h3;
                    dtl[(size_t)row * 64 + pc0] = to_tf32(v[0] - h0);
                    dtl[(size_t)row * 64 + pc1] = to_tf32(v[1] - h1);
                    dtl[(size_t)(row + 8) * 64 + pc0] = to_tf32(v[2] - h2);
                    dtl[(size_t)(row + 8) * 64 + pc1] = to_tf32(v[3] - h3);
                } else if (col < 96) {
                    float* bp  = bc + (size_t)row * 32 + (col - 64);
                    float* bp2 = bp + 8 * 32;
                    bp [0] = v[0]; bp [1] = v[1];
                    bp2[0] = v[2]; bp2[1] = v[3];
                }
            }
        }
    }
}

// ---------------- tf32 round + p16 (hidden) ----------------
__global__ void round_perm_kernel(const float* __restrict__ in, float* __restrict__ out, int n)
{
    int i = blockIdx.x * 256 + threadIdx.x;
    if (i < n) out[p16(i)] = to_tf32(in[i]);
}

// ---------------- transpose + tf32 round + p16 (hi only) ----------------
__global__ void transpose_round_kernel(const float* __restrict__ W, float* __restrict__ WT,
                                       int K, int N)
{
    __shared__ float t[32][33];
    const int n0 = blockIdx.x * 32;
    const int k0 = blockIdx.y * 32;
    const int tx = threadIdx.x, ty = threadIdx.y;
    #pragma unroll
    for (int i = 0; i < 4; i++)
        t[ty + i * 8][tx] = W[(size_t)(k0 + ty + i * 8) * N + n0 + tx];
    __syncthreads();
    #pragma unroll
    for (int i = 0; i < 4; i++)
        WT[(size_t)(n0 + ty + i * 8) * K + p16(k0 + tx)] = to_tf32(t[tx][ty + i * 8]);
}

// ---------------- transpose + split + p16 (hi & lo), guarded N ----------------
__global__ void transpose_split_kernel(const float* __restrict__ W,
                                       float* __restrict__ Th, float* __restrict__ Tl,
                                       int K, int N)
{
    __shared__ float t[32][33];
    const int n0 = blockIdx.x * 32;
    const int k0 = blockIdx.y * 32;
    const int tx = threadIdx.x, ty = threadIdx.y;
    #pragma unroll
    for (int i = 0; i < 4; i++)
        t[ty + i * 8][tx] = (n0 + tx < N) ? W[(size_t)(k0 + ty + i * 8) * N + n0 + tx] : 0.f;
    __syncthreads();
    #pragma unroll
    for (int i = 0; i < 4; i++) {
        int n = n0 + ty + i * 8;
        if (n < N) {
            float v = t[tx][ty + i * 8];
            float h = to_tf32(v);
            int pk = p16(k0 + tx);
            Th[(size_t)n * K + pk] = h;
            Tl[(size_t)n * K + pk] = to_tf32(v - h);
        }
    }
}

// ---------------- causal depthwise conv (K=4) + silu; emits fp32 + hi/lo(p16) + silu(z) ----------------
__global__ void conv_silu_kernel(const float* __restrict__ xz,
                                 const float* __restrict__ cw,
                                 const float* __restrict__ cb,
                                 float* __restrict__ xo,
                                 float* __restrict__ xh, float* __restrict__ xl,
                                 float* __restrict__ zso)
{
    int idx = blockIdx.x * 256 + threadIdx.x;
    int d   = idx & (DINNER - 1);
    int row = idx >> 11;
    int t   = row & (SEQLEN - 1);

    float w0 = cw[d*4+0], w1 = cw[d*4+1], w2 = cw[d*4+2], w3 = cw[d*4+3];
    size_t base = (size_t)row * 4096 + d;
    float acc = cb[d] + xz[base] * w3;
    if (t >= 1) acc = fmaf(xz[base - 4096],     w2, acc);
    if (t >= 2) acc = fmaf(xz[base - 2 * 4096], w1, acc);
    if (t >= 3) acc = fmaf(xz[base - 3 * 4096], w0, acc);
    float xv = acc * (1.f / (1.f + __expf(-acc)));
    xo[idx] = xv;
    float h = to_tf32(xv);
    size_t pidx = (size_t)row * DINNER + p16(d);
    xh[pidx] = h;
    xl[pidx] = to_tf32(xv - h);

    float zv = xz[(size_t)row * 4096 + DINNER + d];
    zso[idx] = zv * (1.f / (1.f + __expf(-zv)));
}

// ---------------- selective scan (BC dense buffer; writes tf32 p16 y) ----------------
__global__ void __launch_bounds__(512) scan_kernel(
    const float* __restrict__ bcin, const float* __restrict__ xs,
    const float* __restrict__ dts,  const float* __restrict__ zss,
    const float* __restrict__ A_log, const float* __restrict__ Dp,
    float* __restrict__ y)
{
    const int b   = blockIdx.y;
    const int d0  = blockIdx.x * 32;
    const int tid = threadIdx.x;
    const int n   = tid & 15;
    const int ch  = tid >> 4;
    const int d   = d0 + ch;

    __shared__ float sBC[64][32];
    __shared__ float sX [64][32];
    __shared__ float sDT[64][32];
    __shared__ float sZ [64][32];
    __shared__ float sY [64][32];

    const float a  = -__expf(A_log[d * DSTATE + n]);
    const float Dd = Dp[d];
    float h = 0.f;

    const size_t rowbase = (size_t)b * SEQLEN;
    for (int t0 = 0; t0 < SEQLEN; t0 += 64) {
        __syncthreads();
        #pragma unroll
        for (int i = 0; i < 4; i++) {
            int j  = tid + i * 512;
            int tl = j >> 5, dd = j & 31;
            size_t r = rowbase + t0 + tl;
            sX [tl][dd] = xs [r * DINNER + d0 + dd];
            sDT[tl][dd] = dts[r * DINNER + d0 + dd];
            sZ [tl][dd] = zss[r * DINNER + d0 + dd];
            sBC[tl][dd] = bcin[r * 32 + dd];
        }
        __syncthreads();

        #pragma unroll 4
        for (int tl = 0; tl < 64; tl++) {
            float dtv = sDT[tl][ch];
            float xv  = sX [tl][ch];
            float Bv  = sBC[tl][n];
            float Cv  = sBC[tl][16 + n];
            float e   = __expf(a * dtv);
            h = fmaf(e, h, dtv * xv * Bv);
            float p = h * Cv;
            p += __shfl_xor_sync(0xffffffffu, p, 1);
            p += __shfl_xor_sync(0xffffffffu, p, 2);
            p += __shfl_xor_sync(0xffffffffu, p, 4);
            p += __shfl_xor_sync(0xffffffffu, p, 8);
            if (n == 0) {
                sY[tl][ch] = fmaf(Dd, xv, p) * sZ[tl][ch];
            }
        }
        __syncthreads();

        #pragma unroll
        for (int i = 0; i < 4; i++) {
            int j  = tid + i * 512;
            int tl = j >> 5, dd = j & 31;
            y[(rowbase + t0 + tl) * DINNER + d0 + p16(dd)] = to_tf32(sY[tl][dd]);
        }
    }
}

// ---------------- launch ----------------
extern "C" void kernel_launch(void* const* d_in, const int* in_sizes, int n_in,
                              void* d_out, int out_size)
{
    const float* hidden    = (const float*)d_in[0];
    const float* in_proj_w = (const float*)d_in[1];
    const float* conv_w    = (const float*)d_in[2];
    const float* conv_b    = (const float*)d_in[3];
    const float* x_proj_w  = (const float*)d_in[4];
    const float* dt_proj_w = (const float*)d_in[5];
    const float* dt_proj_b = (const float*)d_in[6];
    const float* A_log     = (const float*)d_in[7];
    const float* Dw        = (const float*)d_in[8];
    const float* out_proj_w= (const float*)d_in[9];
    float* out = (float*)d_out;

    float *p_xz, *p_x, *p_xh, *p_xl, *p_zs, *p_bc, *p_dth, *p_dtl, *p_dt, *p_y;
    float *p_hidr, *p_w1t, *p_w2t, *p_xwh, *p_xwl, *p_dwh, *p_dwl;
    cudaGetSymbolAddress((void**)&p_xz,   g_xz);
    cudaGetSymbolAddress((void**)&p_x,    g_x);
    cudaGetSymbolAddress((void**)&p_xh,   g_xh);
    cudaGetSymbolAddress((void**)&p_xl,   g_xl);
    cudaGetSymbolAddress((void**)&p_zs,   g_zs);
    cudaGetSymbolAddress((void**)&p_bc,   g_bc);
    cudaGetSymbolAddress((void**)&p_dth,  g_dth);
    cudaGetSymbolAddress((void**)&p_dtl,  g_dtl);
    cudaGetSymbolAddress((void**)&p_dt,   g_dt);
    cudaGetSymbolAddress((void**)&p_y,    g_y);
    cudaGetSymbolAddress((void**)&p_hidr, g_hidr);
    cudaGetSymbolAddress((void**)&p_w1t,  g_w1t);
    cudaGetSymbolAddress((void**)&p_w2t,  g_w2t);
    cudaGetSymbolAddress((void**)&p_xwh,  g_xwh);
    cudaGetSymbolAddress((void**)&p_xwl,  g_xwl);
    cudaGetSymbolAddress((void**)&p_dwh,  g_dwh);
    cudaGetSymbolAddress((void**)&p_dwl,  g_dwl);

    cudaFuncSetAttribute(gemm_big,      cudaFuncAttributeMaxDynamicSharedMemorySize, BG_SMEM);
    cudaFuncSetAttribute(gemm_split<1>, cudaFuncAttributeMaxDynamicSharedMemorySize, SP_SMEM);
    cudaFuncSetAttribute(gemm_split<2>, cudaFuncAttributeMaxDynamicSharedMemorySize, SP_SMEM);

    // 0) preprocessing
    round_perm_kernel<<<(NROWS * DMODEL + 255) / 256, 256>>>(hidden, p_hidr, NROWS * DMODEL);
    transpose_round_kernel<<<dim3(4096 / 32, DMODEL / 32), dim3(32, 8)>>>(in_proj_w, p_w1t, DMODEL, 4096);
    transpose_round_kernel<<<dim3(DMODEL / 32, DINNER / 32), dim3(32, 8)>>>(out_proj_w, p_w2t, DINNER, DMODEL);
    transpose_split_kernel<<<dim3(3, DINNER / 32), dim3(32, 8)>>>(x_proj_w, p_xwh, p_xwl, DINNER, 96);
    transpose_split_kernel<<<dim3(DINNER / 32, DTRANK / 32), dim3(32, 8)>>>(dt_proj_w, p_dwh, p_dwl, DTRANK, DINNER);

    // 1) xz = hidden @ in_proj_w (8192 x 4096, K=1024)
    gemm_big<<<dim3(4096 / 256, NROWS / 128), 256, BG_SMEM>>>(p_hidr, p_w1t, p_xz, DMODEL, 4096);

    // 2) conv + silu (fp32 + tf32 hi/lo p16); silu(z)
    conv_silu_kernel<<<(NROWS * DINNER) / 256, 256>>>(p_xz, conv_w, conv_b, p_x, p_xh, p_xl, p_zs);

    // 3) x_dbl = x @ x_proj_w (N=96 padded to 128, K=2048): dt hi/lo + BC buffers
    gemm_split<2><<<dim3(1, NROWS / 128), 256, SP_SMEM>>>(
        p_xh, p_xl, p_xwh, p_xwl, nullptr, nullptr, p_dth, p_dtl, p_bc, DINNER, 0);

    // 4) dt = softplus(dt_in @ dt_proj_w + b) (N=2048, K=64)
    gemm_split<1><<<dim3(DINNER / 128, NROWS / 128), 256, SP_SMEM>>>(
        p_dth, p_dtl, p_dwh, p_dwl, dt_proj_b, p_dt, nullptr, nullptr, nullptr, DTRANK, DINNER);

    // 5) selective scan -> y (silu(z)-gated), tf32 p16
    scan_kernel<<<dim3(64, BATCHN), 512>>>(p_bc, p_x, p_dt, p_zs, A_log, Dw, p_y);

    // 6) out = y @ out_proj_w (N=1024, K=2048)
    gemm_big<<<dim3(DMODEL / 256, NROWS / 128), 256, BG_SMEM>>>(p_y, p_w2t, out, DINNER, DMODEL);
}

// round 6
// speedup vs baseline: 1.4034x; 1.0768x over previous
#include <cuda_runtime.h>
#include <cstdint>

#define BATCHN 4
#define SEQLEN 2048
#define DMODEL 1024
#define DINNER 2048
#define DSTATE 16
#define DTRANK 64
#define NROWS (BATCHN*SEQLEN)   /* 8192 */

// ---------------- scratch (static device globals; no allocations) ----------------
__device__ float g_xz  [NROWS*4096];     // in_proj output (x | z)
__device__ float g_x   [NROWS*DINNER];   // conv+silu output (fp32, for scan)
__device__ float g_xh  [NROWS*DINNER];   // conv+silu tf32 hi, p16
__device__ float g_xl  [NROWS*DINNER];   // conv+silu tf32 lo, p16
__device__ float g_zs  [NROWS*DINNER];   // silu(z)
__device__ float g_xp  [4*NROWS*128];    // x_proj split-K partials
__device__ float g_bc  [NROWS*32];       // B|C (fp32), dense
__device__ float g_dth [NROWS*DTRANK];   // dt_in hi, p16
__device__ float g_dtl [NROWS*DTRANK];   // dt_in lo, p16
__device__ float g_dt  [NROWS*DINNER];   // softplus(dt_in @ dt_proj_w + b)
__device__ float g_y   [NROWS*DINNER];   // scan out * silu(z), tf32, p16
__device__ float g_hidr[NROWS*DMODEL];   // hidden, tf32, p16
__device__ float g_w1t [4096*DMODEL];    // in_proj_w^T, tf32, p16
__device__ float g_w2t [DMODEL*DINNER];  // out_proj_w^T, tf32, p16
__device__ float g_xwh [128*DINNER];     // x_proj_w^T hi (rows 96..127 stay zero)
__device__ float g_xwl [128*DINNER];     // x_proj_w^T lo
__device__ float g_dwh [DINNER*DTRANK];  // dt_proj_w^T hi
__device__ float g_dwl [DINNER*DTRANK];  // dt_proj_w^T lo

// ---------------- helpers ----------------
__device__ __forceinline__ float to_tf32(float x) {
    uint32_t u;
    asm("cvt.rna.tf32.f32 %0, %1;" : "=r"(u) : "f"(x));
    return __uint_as_float(u);
}

// permute k within groups of 16: (k,k+4,k+8,k+12) become 4 adjacent words
__device__ __forceinline__ int p16(int k) {
    return (k & ~15) | ((k & 3) << 2) | ((k >> 2) & 3);
}

__device__ __forceinline__ void mma8(float* d, const uint32_t* a, const uint32_t* b) {
    asm volatile(
        "mma.sync.aligned.m16n8k8.row.col.f32.tf32.tf32.f32 "
        "{%0,%1,%2,%3}, {%4,%5,%6,%7}, {%8,%9}, {%0,%1,%2,%3};\n"
        : "+f"(d[0]), "+f"(d[1]), "+f"(d[2]), "+f"(d[3])
        : "r"(a[0]), "r"(a[1]), "r"(a[2]), "r"(a[3]), "r"(b[0]), "r"(b[1]));
}

__device__ __forceinline__ void cp_async16(uint32_t smem_addr, const void* gmem) {
    asm volatile("cp.async.cg.shared.global [%0], [%1], 16;" :: "r"(smem_addr), "l"(gmem));
}

__device__ __forceinline__ float softplus_fast(float v) {
    return fmaxf(v, 0.f) + __logf(1.f + __expf(-fabsf(v)));
}

// ================= big GEMM: 128x256 tile, 5-stage, 1 sync/tile =================
#define BG_STG (384*16)                 /* words per stage: A 128x16 then B 256x16 */
#define BG_SMEM (5*BG_STG*4)            /* 122880 bytes */

__global__ void __launch_bounds__(256) gemm_big(
    const float* __restrict__ A, const float* __restrict__ BT, float* __restrict__ C,
    int K, int ldc)
{
    extern __shared__ float sm[];
    const uint32_t sb = (uint32_t)__cvta_generic_to_shared(sm);

    const int tid  = threadIdx.x;
    const int lane = tid & 31;
    const int w    = tid >> 5;
    const int wr   = w >> 2;        // 0..1
    const int wc   = w & 3;         // 0..3
    const int tig  = lane & 3;
    const int g    = lane >> 2;
    const int m0   = blockIdx.y * 128;
    const int n0   = blockIdx.x * 256;

    float acc[4][8][4];
    #pragma unroll
    for (int i = 0; i < 4; i++)
        #pragma unroll
        for (int j = 0; j < 8; j++)
            #pragma unroll
            for (int q = 0; q < 4; q++) acc[i][j][q] = 0.f;

    const int nc = K >> 4;

    auto copy = [&](int c, int s) {
        const float* Ab = A + (size_t)m0 * K + c * 16;
        #pragma unroll
        for (int i = 0; i < 2; i++) {
            int idx = tid + i * 256;
            int r = idx >> 2, sg = (idx & 3) * 4;
            cp_async16(sb + (uint32_t)(s * BG_STG + r * 16 + sg) * 4,
                       Ab + (size_t)r * K + sg);
        }
        const float* Bb = BT + (size_t)n0 * K + c * 16;
        #pragma unroll
        for (int i = 0; i < 4; i++) {
            int idx = tid + i * 256;
            int r = idx >> 2, sg = (idx & 3) * 4;
            cp_async16(sb + (uint32_t)(s * BG_STG + 2048 + r * 16 + sg) * 4,
                       Bb + (size_t)r * K + sg);
        }
    };

    #pragma unroll
    for (int p = 0; p < 4; p++) {
        if (p < nc) copy(p, p);
        asm volatile("cp.async.commit_group;");
    }

    for (int c = 0; c < nc; c++) {
        const int s = c % 5;
        asm volatile("cp.async.wait_group 3;");
        __syncthreads();

        const float* as = sm + s * BG_STG;
        const float* bs = as + 2048;

        uint4 av[4][2];
        #pragma unroll
        for (int mf = 0; mf < 4; mf++) {
            int mr = wr * 64 + mf * 16 + g;
            av[mf][0] = *reinterpret_cast<const uint4*>(as + mr * 16 + 4 * tig);
            av[mf][1] = *reinterpret_cast<const uint4*>(as + (mr + 8) * 16 + 4 * tig);
        }
        #pragma unroll
        for (int nh = 0; nh < 2; nh++) {           // process B in halves (reg pressure)
            uint4 bv[4];
            #pragma unroll
            for (int nf = 0; nf < 4; nf++) {
                int ncol = wc * 64 + (nh * 4 + nf) * 8 + g;
                bv[nf] = *reinterpret_cast<const uint4*>(bs + ncol * 16 + 4 * tig);
            }
            #pragma unroll
            for (int mf = 0; mf < 4; mf++) {
                uint32_t a0[4] = {av[mf][0].x, av[mf][1].x, av[mf][0].y, av[mf][1].y};
                uint32_t a8[4] = {av[mf][0].z, av[mf][1].z, av[mf][0].w, av[mf][1].w};
                #pragma unroll
                for (int nf = 0; nf < 4; nf++) {
                    uint32_t b0[2] = {bv[nf].x, bv[nf].y};
                    uint32_t b8[2] = {bv[nf].z, bv[nf].w};
                    mma8(acc[mf][nh * 4 + nf], a0, b0);
                    mma8(acc[mf][nh * 4 + nf], a8, b8);
                }
            }
        }

        if (c + 4 < nc) copy(c + 4, (c + 4) % 5);
        asm volatile("cp.async.commit_group;");
    }

    // ---- epilogue ----
    #pragma unroll
    for (int mf = 0; mf < 4; mf++) {
        int row = m0 + wr * 64 + mf * 16 + g;
        #pragma unroll
        for (int nf = 0; nf < 8; nf++) {
            int col = n0 + wc * 64 + nf * 8 + 2 * tig;
            float* cp  = C + (size_t)row * ldc + col;
            float* cp2 = cp + (size_t)8 * ldc;
            cp [0] = acc[mf][nf][0]; cp [1] = acc[mf][nf][1];
            cp2[0] = acc[mf][nf][2]; cp2[1] = acc[mf][nf][3];
        }
    }
}

// ================= split (3xTF32) GEMM: 128x128 tile, 3-stage, split-K capable =================
// EPI 0: raw fp32 partials -> C + blockIdx.z*cstride  (ldc)
// EPI 1: softplus(v+bias[col]) -> C
#define SP_STG (4*128*16)               /* words: Ahi, Alo, Bhi, Blo */
#define SP_SMEM (3*SP_STG*4)            /* 98304 bytes */

template<int EPI>
__global__ void __launch_bounds__(256) gemm_split(
    const float* __restrict__ Ah, const float* __restrict__ Al,
    const float* __restrict__ Bh, const float* __restrict__ Bl,
    const float* __restrict__ bias, float* __restrict__ C,
    int Kc, int lda, int ldc, size_t cstride)
{
    extern __shared__ float sm[];
    const uint32_t sb = (uint32_t)__cvta_generic_to_shared(sm);

    const int tid  = threadIdx.x;
    const int lane = tid & 31;
    const int w    = tid >> 5;
    const int wr   = w >> 2;        // 0..1
    const int wc   = w & 3;         // 0..3
    const int tig  = lane & 3;
    const int g    = lane >> 2;
    const int m0   = blockIdx.y * 128;
    const int n0   = blockIdx.x * 128;
    const int z    = blockIdx.z;

    const float* Ahp = Ah + (size_t)m0 * lda + (size_t)z * Kc;
    const float* Alp = Al + (size_t)m0 * lda + (size_t)z * Kc;
    const float* Bhp = Bh + (size_t)n0 * lda + (size_t)z * Kc;
    const float* Blp = Bl + (size_t)n0 * lda + (size_t)z * Kc;
    float* Cp = C + (size_t)z * cstride;

    float acc[4][4][4];
    #pragma unroll
    for (int i = 0; i < 4; i++)
        #pragma unroll
        for (int j = 0; j < 4; j++)
            #pragma unroll
            for (int q = 0; q < 4; q++) acc[i][j][q] = 0.f;

    const int nc = Kc >> 4;

    auto copy = [&](int c, int s) {
        #pragma unroll
        for (int i = 0; i < 2; i++) {
            int idx = tid + i * 256;
            int r = idx >> 2, sg = (idx & 3) * 4;
            size_t go = (size_t)r * lda + c * 16 + sg;
            uint32_t so = (uint32_t)(s * SP_STG + r * 16 + sg) * 4;
            cp_async16(sb + so,             Ahp + go);
            cp_async16(sb + so + 2048 * 4,  Alp + go);
            cp_async16(sb + so + 4096 * 4,  Bhp + go);
            cp_async16(sb + so + 6144 * 4,  Blp + go);
        }
    };

    #pragma unroll
    for (int p = 0; p < 2; p++) {
        if (p < nc) copy(p, p);
        asm volatile("cp.async.commit_group;");
    }

    int s = 0;
    for (int c = 0; c < nc; c++) {
        asm volatile("cp.async.wait_group 1;");
        __syncthreads();

        const float* ah = sm + s * SP_STG;
        const float* al = ah + 2048;
        const float* bh = ah + 4096;
        const float* bl = ah + 6144;

        uint4 avh[4][2], avl[4][2], bvh[4], bvl[4];
        #pragma unroll
        for (int mf = 0; mf < 4; mf++) {
            int mr = wr * 64 + mf * 16 + g;
            avh[mf][0] = *reinterpret_cast<const uint4*>(ah + mr * 16 + 4 * tig);
            avh[mf][1] = *reinterpret_cast<const uint4*>(ah + (mr + 8) * 16 + 4 * tig);
            avl[mf][0] = *reinterpret_cast<const uint4*>(al + mr * 16 + 4 * tig);
            avl[mf][1] = *reinterpret_cast<const uint4*>(al + (mr + 8) * 16 + 4 * tig);
        }
        #pragma unroll
        for (int nf = 0; nf < 4; nf++) {
            int ncol = wc * 32 + nf * 8 + g;
            bvh[nf] = *reinterpret_cast<const uint4*>(bh + ncol * 16 + 4 * tig);
            bvl[nf] = *reinterpret_cast<const uint4*>(bl + ncol * 16 + 4 * tig);
        }
        #pragma unroll
        for (int mf = 0; mf < 4; mf++) {
            uint32_t ah0[4] = {avh[mf][0].x, avh[mf][1].x, avh[mf][0].y, avh[mf][1].y};
            uint32_t ah8[4] = {avh[mf][0].z, avh[mf][1].z, avh[mf][0].w, avh[mf][1].w};
            uint32_t al0[4] = {avl[mf][0].x, avl[mf][1].x, avl[mf][0].y, avl[mf][1].y};
            uint32_t al8[4] = {avl[mf][0].z, avl[mf][1].z, avl[mf][0].w, avl[mf][1].w};
            #pragma unroll
            for (int nf = 0; nf < 4; nf++) {
                uint32_t bh0[2] = {bvh[nf].x, bvh[nf].y};
                uint32_t bh8[2] = {bvh[nf].z, bvh[nf].w};
                uint32_t bl0[2] = {bvl[nf].x, bvl[nf].y};
                uint32_t bl8[2] = {bvl[nf].z, bvl[nf].w};
                mma8(acc[mf][nf], ah0, bh0);
                mma8(acc[mf][nf], ah0, bl0);
                mma8(acc[mf][nf], al0, bh0);
                mma8(acc[mf][nf], ah8, bh8);
                mma8(acc[mf][nf], ah8, bl8);
                mma8(acc[mf][nf], al8, bh8);
            }
        }

        if (c + 2 < nc) copy(c + 2, (c + 2) % 3);
        asm volatile("cp.async.commit_group;");
        s = (s + 1 == 3) ? 0 : s + 1;
    }

    // ---- epilogue ----
    #pragma unroll
    for (int mf = 0; mf < 4; mf++) {
        int row = m0 + wr * 64 + mf * 16 + g;
        #pragma unroll
        for (int nf = 0; nf < 4; nf++) {
            int col = n0 + wc * 32 + nf * 8 + 2 * tig;
            float v[4] = {acc[mf][nf][0], acc[mf][nf][1], acc[mf][nf][2], acc[mf][nf][3]};
            if (EPI == 1) {
                float b0 = bias[col], b1 = bias[col + 1];
                float* cp  = Cp + (size_t)row * ldc + col;
                float* cp2 = cp + (size_t)8 * ldc;
                cp [0] = softplus_fast(v[0] + b0); cp [1] = softplus_fast(v[1] + b1);
                cp2[0] = softplus_fast(v[2] + b0); cp2[1] = softplus_fast(v[3] + b1);
            } else {
                float* cp  = Cp + (size_t)row * ldc + col;
                float* cp2 = cp + (size_t)8 * ldc;
                cp [0] = v[0]; cp [1] = v[1];
                cp2[0] = v[2]; cp2[1] = v[3];
            }
        }
    }
}

// ---------------- x_proj split-K reduce: partials -> dt hi/lo (p16) + bc ----------------
__global__ void xproj_reduce_kernel(const float* __restrict__ part,
                                    float* __restrict__ dth, float* __restrict__ dtl,
                                    float* __restrict__ bc)
{
    int i = blockIdx.x * 256 + threadIdx.x;          // over NROWS*96
    if (i >= NROWS * 96) return;
    int row = i / 96, col = i - row * 96;
    size_t o = (size_t)row * 128 + col;
    const size_t cs = (size_t)NROWS * 128;
    float s = part[o] + part[o + cs] + part[o + 2 * cs] + part[o + 3 * cs];
    if (col < 64) {
        float h = to_tf32(s);
        dth[(size_t)row * 64 + p16(col)] = h;
        dtl[(size_t)row * 64 + p16(col)] = to_tf32(s - h);
    } else {
        bc[(size_t)row * 32 + (col - 64)] = s;
    }
}

// ---------------- tf32 round + p16 (hidden) ----------------
__global__ void round_perm_kernel(const float* __restrict__ in, float* __restrict__ out, int n)
{
    int i = blockIdx.x * 256 + threadIdx.x;
    if (i < n) out[p16(i)] = to_tf32(in[i]);
}

// ---------------- transpose + tf32 round + p16 (hi only) ----------------
__global__ void transpose_round_kernel(const float* __restrict__ W, float* __restrict__ WT,
                                       int K, int N)
{
    __shared__ float t[32][33];
    const int n0 = blockIdx.x * 32;
    const int k0 = blockIdx.y * 32;
    const int tx = threadIdx.x, ty = threadIdx.y;
    #pragma unroll
    for (int i = 0; i < 4; i++)
        t[ty + i * 8][tx] = W[(size_t)(k0 + ty + i * 8) * N + n0 + tx];
    __syncthreads();
    #pragma unroll
    for (int i = 0; i < 4; i++)
        WT[(size_t)(n0 + ty + i * 8) * K + p16(k0 + tx)] = to_tf32(t[tx][ty + i * 8]);
}

// ---------------- transpose + split + p16 (hi & lo); both small weights in one launch ----------------
__device__ __forceinline__ void transpose_split_body(
    const float* __restrict__ W, float* __restrict__ Th, float* __restrict__ Tl,
    int K, int N, int bx, int by)
{
    __shared__ float t[32][33];
    const int n0 = bx * 32;
    const int k0 = by * 32;
    const int tx = threadIdx.x, ty = threadIdx.y;
    #pragma unroll
    for (int i = 0; i < 4; i++)
        t[ty + i * 8][tx] = (n0 + tx < N) ? W[(size_t)(k0 + ty + i * 8) * N + n0 + tx] : 0.f;
    __syncthreads();
    #pragma unroll
    for (int i = 0; i < 4; i++) {
        int n = n0 + ty + i * 8;
        if (n < N) {
            float v = t[tx][ty + i * 8];
            float h = to_tf32(v);
            int pk = p16(k0 + tx);
            Th[(size_t)n * K + pk] = h;
            Tl[(size_t)n * K + pk] = to_tf32(v - h);
        }
    }
}

// job A: x_proj_w [2048 x 96] -> xwh/xwl (K=2048 cols, N=96): 3 x 64 = 192 blocks
// job B: dt_proj_w [64 x 2048] -> dwh/dwl (K=64, N=2048): 64 x 2 = 128 blocks
__global__ void transpose_split_both_kernel(
    const float* __restrict__ Wx, float* __restrict__ xwh, float* __restrict__ xwl,
    const float* __restrict__ Wd, float* __restrict__ dwh, float* __restrict__ dwl)
{
    int b = blockIdx.x;
    if (b < 192) {
        transpose_split_body(Wx, xwh, xwl, DINNER, 96, b % 3, b / 3);
    } else {
        b -= 192;
        transpose_split_body(Wd, dwh, dwl, DTRANK, DINNER, b % 64, b / 64);
    }
}

// ---------------- causal depthwise conv (K=4) + silu; emits fp32 + hi/lo(p16) + silu(z) ----------------
__global__ void conv_silu_kernel(const float* __restrict__ xz,
                                 const float* __restrict__ cw,
                                 const float* __restrict__ cb,
                                 float* __restrict__ xo,
                                 float* __restrict__ xh, float* __restrict__ xl,
                                 float* __restrict__ zso)
{
    int idx = blockIdx.x * 256 + threadIdx.x;
    int d   = idx & (DINNER - 1);
    int row = idx >> 11;
    int t   = row & (SEQLEN - 1);

    float w0 = cw[d*4+0], w1 = cw[d*4+1], w2 = cw[d*4+2], w3 = cw[d*4+3];
    size_t base = (size_t)row * 4096 + d;
    float acc = cb[d] + xz[base] * w3;
    if (t >= 1) acc = fmaf(xz[base - 4096],     w2, acc);
    if (t >= 2) acc = fmaf(xz[base - 2 * 4096], w1, acc);
    if (t >= 3) acc = fmaf(xz[base - 3 * 4096], w0, acc);
    float xv = acc * (1.f / (1.f + __expf(-acc)));
    xo[idx] = xv;
    float h = to_tf32(xv);
    size_t pidx = (size_t)row * DINNER + p16(d);
    xh[pidx] = h;
    xl[pidx] = to_tf32(xv - h);

    float zv = xz[(size_t)row * 4096 + DINNER + d];
    zso[idx] = zv * (1.f / (1.f + __expf(-zv)));
}

// ---------------- selective scan: 256 threads = 16 channels x 16 states ----------------
__global__ void __launch_bounds__(256) scan_kernel(
    const float* __restrict__ bcin, const float* __restrict__ xs,
    const float* __restrict__ dts,  const float* __restrict__ zss,
    const float* __restrict__ A_log, const float* __restrict__ Dp,
    float* __restrict__ y)
{
    const int b   = blockIdx.y;
    const int d0  = blockIdx.x * 16;
    const int tid = threadIdx.x;
    const int n   = tid & 15;
    const int ch  = tid >> 4;           // 0..15
    const int d   = d0 + ch;

    __shared__ float sBC[64][32];
    __shared__ float sX [64][16];
    __shared__ float sDT[64][16];
    __shared__ float sZ [64][16];
    __shared__ float sY [64][16];

    const float a  = -__expf(A_log[d * DSTATE + n]);
    const float Dd = Dp[d];
    float h = 0.f;

    const size_t rowbase = (size_t)b * SEQLEN;
    for (int t0 = 0; t0 < SEQLEN; t0 += 64) {
        __syncthreads();
        #pragma unroll
        for (int i = 0; i < 4; i++) {
            int j  = tid + i * 256;      // 0..1023
            int tl = j >> 4, dd = j & 15;
            size_t r = rowbase + t0 + tl;
            sX [tl][dd] = xs [r * DINNER + d0 + dd];
            sDT[tl][dd] = dts[r * DINNER + d0 + dd];
            sZ [tl][dd] = zss[r * DINNER + d0 + dd];
        }
        #pragma unroll
        for (int i = 0; i < 8; i++) {
            int j  = tid + i * 256;      // 0..2047
            int tl = j >> 5, dd = j & 31;
            sBC[tl][dd] = bcin[(rowbase + t0 + tl) * 32 + dd];
        }
        __syncthreads();

        #pragma unroll 4
        for (int tl = 0; tl < 64; tl++) {
            float dtv = sDT[tl][ch];
            float xv  = sX [tl][ch];
            float Bv  = sBC[tl][n];
            float Cv  = sBC[tl][16 + n];
            float e   = __expf(a * dtv);
            h = fmaf(e, h, dtv * xv * Bv);
            float p = h * Cv;
            p += __shfl_xor_sync(0xffffffffu, p, 1);
            p += __shfl_xor_sync(0xffffffffu, p, 2);
            p += __shfl_xor_sync(0xffffffffu, p, 4);
            p += __shfl_xor_sync(0xffffffffu, p, 8);
            if (n == 0) {
                sY[tl][ch] = fmaf(Dd, xv, p) * sZ[tl][ch];
            }
        }
        __syncthreads();

        #pragma unroll
        for (int i = 0; i < 4; i++) {
            int j  = tid + i * 256;
            int tl = j >> 4, dd = j & 15;
            y[(rowbase + t0 + tl) * DINNER + d0 + p16(dd)] = to_tf32(sY[tl][dd]);
        }
    }
}

// ---------------- launch ----------------
extern "C" void kernel_launch(void* const* d_in, const int* in_sizes, int n_in,
                              void* d_out, int out_size)
{
    const float* hidden    = (const float*)d_in[0];
    const float* in_proj_w = (const float*)d_in[1];
    const float* conv_w    = (const float*)d_in[2];
    const float* conv_b    = (const float*)d_in[3];
    const float* x_proj_w  = (const float*)d_in[4];
    const float* dt_proj_w = (const float*)d_in[5];
    const float* dt_proj_b = (const float*)d_in[6];
    const float* A_log     = (const float*)d_in[7];
    const float* Dw        = (const float*)d_in[8];
    const float* out_proj_w= (const float*)d_in[9];
    float* out = (float*)d_out;

    float *p_xz, *p_x, *p_xh, *p_xl, *p_zs, *p_xp, *p_bc, *p_dth, *p_dtl, *p_dt, *p_y;
    float *p_hidr, *p_w1t, *p_w2t, *p_xwh, *p_xwl, *p_dwh, *p_dwl;
    cudaGetSymbolAddress((void**)&p_xz,   g_xz);
    cudaGetSymbolAddress((void**)&p_x,    g_x);
    cudaGetSymbolAddress((void**)&p_xh,   g_xh);
    cudaGetSymbolAddress((void**)&p_xl,   g_xl);
    cudaGetSymbolAddress((void**)&p_zs,   g_zs);
    cudaGetSymbolAddress((void**)&p_xp,   g_xp);
    cudaGetSymbolAddress((void**)&p_bc,   g_bc);
    cudaGetSymbolAddress((void**)&p_dth,  g_dth);
    cudaGetSymbolAddress((void**)&p_dtl,  g_dtl);
    cudaGetSymbolAddress((void**)&p_dt,   g_dt);
    cudaGetSymbolAddress((void**)&p_y,    g_y);
    cudaGetSymbolAddress((void**)&p_hidr, g_hidr);
    cudaGetSymbolAddress((void**)&p_w1t,  g_w1t);
    cudaGetSymbolAddress((void**)&p_w2t,  g_w2t);
    cudaGetSymbolAddress((void**)&p_xwh,  g_xwh);
    cudaGetSymbolAddress((void**)&p_xwl,  g_xwl);
    cudaGetSymbolAddress((void**)&p_dwh,  g_dwh);
    cudaGetSymbolAddress((void**)&p_dwl,  g_dwl);

    cudaFuncSetAttribute(gemm_big,      cudaFuncAttributeMaxDynamicSharedMemorySize, BG_SMEM);
    cudaFuncSetAttribute(gemm_split<0>, cudaFuncAttributeMaxDynamicSharedMemorySize, SP_SMEM);
    cudaFuncSetAttribute(gemm_split<1>, cudaFuncAttributeMaxDynamicSharedMemorySize, SP_SMEM);

    // 0) preprocessing (4 launches so gemm_big is launch #5 -> ncu -s 5 profiles it)
    round_perm_kernel<<<(NROWS * DMODEL + 255) / 256, 256>>>(hidden, p_hidr, NROWS * DMODEL);
    transpose_round_kernel<<<dim3(4096 / 32, DMODEL / 32), dim3(32, 8)>>>(in_proj_w, p_w1t, DMODEL, 4096);
    transpose_round_kernel<<<dim3(DMODEL / 32, DINNER / 32), dim3(32, 8)>>>(out_proj_w, p_w2t, DINNER, DMODEL);
    transpose_split_both_kernel<<<320, dim3(32, 8)>>>(x_proj_w, p_xwh, p_xwl, dt_proj_w, p_dwh, p_dwl);

    // 1) xz = hidden @ in_proj_w (8192 x 4096, K=1024)   [launch #5 - profiled]
    gemm_big<<<dim3(4096 / 256, NROWS / 128), 256, BG_SMEM>>>(p_hidr, p_w1t, p_xz, DMODEL, 4096);

    // 2) conv + silu (fp32 + tf32 hi/lo p16); silu(z)
    conv_silu_kernel<<<(NROWS * DINNER) / 256, 256>>>(p_xz, conv_w, conv_b, p_x, p_xh, p_xl, p_zs);

    // 3) x_dbl partials = x @ x_proj_w, split-K x4 (chunks of 512)
    gemm_split<0><<<dim3(1, NROWS / 128, 4), 256, SP_SMEM>>>(
        p_xh, p_xl, p_xwh, p_xwl, nullptr, p_xp, 512, DINNER, 128, (size_t)NROWS * 128);

    // 3b) reduce partials -> dt hi/lo + bc
    xproj_reduce_kernel<<<(NROWS * 96 + 255) / 256, 256>>>(p_xp, p_dth, p_dtl, p_bc);

    // 4) dt = softplus(dt_in @ dt_proj_w + b) (N=2048, K=64)
    gemm_split<1><<<dim3(DINNER / 128, NROWS / 128, 1), 256, SP_SMEM>>>(
        p_dth, p_dtl, p_dwh, p_dwl, dt_proj_b, p_dt, DTRANK, DTRANK, DINNER, 0);

    // 5) selective scan -> y (silu(z)-gated), tf32 p16
    scan_kernel<<<dim3(128, BATCHN), 256>>>(p_bc, p_x, p_dt, p_zs, A_log, Dw, p_y);

    // 6) out = y @ out_proj_w (N=1024, K=2048)
    gemm_big<<<dim3(DMODEL / 256, NROWS / 128), 256, BG_SMEM>>>(p_y, p_w2t, out, DINNER, DMODEL);
}